// round 6
// baseline (speedup 1.0000x reference)
#include <cuda_runtime.h>
#include <mma.h>
#include <math.h>

using namespace nvcuda;

// ---------------------------------------------------------------------------
// Problem constants: B=32, S=T=64, E=H=512, G=3H=1536, V=32000
// ---------------------------------------------------------------------------

// Scratch offsets (in floats) into one big __device__ buffer
#define OF_ESRC 0ul            /* 2048*512  */
#define OF_ETGT 1048576ul      /* 2048*512  */
#define OF_GXF  2097152ul      /* 2048*1536 */
#define OF_GXB  5242880ul      /* 2048*1536 */
#define OF_DGX  8388608ul      /* 2048*1536 */
#define OF_SRCH 11534336ul     /* 2048*1024 */
#define OF_UH   13631488ul     /* 2048*512  */
#define OF_DOUT 14680064ul     /* 2048*512  */
#define OF_HF   15728640ul     /* 2*32*512 double buffer */
#define OF_HB   15761408ul     /* 2*32*512 */
#define OF_HD   15794176ul     /* 2*32*512 */
#define OF_CTX  15826944ul     /* 32*1024 */
#define OF_PART 15859712ul     /* 6*32*1536 dec split-K partials */
#define OF_LP   16154624ul     /* 2048*500*2 logits (max,sumexp) partials */
#define OF_CON  18202624ul     /* 2048 */
#define OF_CNT  18204672ul     /* 2048 */
#define BUF_TOTAL 18206720ul

__device__ __align__(16) float g_buf[BUF_TOTAL];

__device__ __forceinline__ float sigm(float x) { return 1.f / (1.f + __expf(-x)); }
__device__ __forceinline__ float dot4(float4 a, float4 b, float acc) {
    acc = fmaf(a.x, b.x, acc); acc = fmaf(a.y, b.y, acc);
    acc = fmaf(a.z, b.z, acc); acc = fmaf(a.w, b.w, acc);
    return acc;
}

// ---------------------------------------------------------------------------
// zero initial hidden states (runs every replay)
// ---------------------------------------------------------------------------
__global__ void k_zero() {
    int i = blockIdx.x * 256 + threadIdx.x;   // grid 64 -> 16384
    g_buf[OF_HF + i] = 0.f;
    g_buf[OF_HB + i] = 0.f;
    g_buf[OF_HD + i] = 0.f;
}

// ---------------------------------------------------------------------------
// embedding gather: row r -> table[ids[r]] (512 floats)
// ---------------------------------------------------------------------------
__global__ void k_embed(const int* __restrict__ ids, const float* __restrict__ tab,
                        size_t out_off) {
    int row = blockIdx.x;
    const float4* src = (const float4*)(tab + (size_t)ids[row] * 512);
    float4* dst = (float4*)(g_buf + out_off + (size_t)row * 512);
    dst[threadIdx.x] = src[threadIdx.x];
}

// ---------------------------------------------------------------------------
// TF32 tensor-core GEMM mainloop (shared by k_gemm_tc and k_logits_tc)
// BM=64, BN=64, BK=16, 128 threads (4 warps, 2x2 layout, 32x32 per warp)
// A[M,K] row-major in g_buf; W[N,K] row-major in global (B = W^T via col_major)
// ---------------------------------------------------------------------------
#define TC_MAINLOOP(A_, lda_, W_, ldw_, K_)                                          \
    int t = threadIdx.x;                                                             \
    int wid = t >> 5;                                                                \
    int wm = (wid >> 1) * 32, wn = (wid & 1) * 32;                                   \
    int r = t >> 1, c8 = (t & 1) * 8;                                                \
    wmma::fragment<wmma::accumulator, 16, 16, 8, float> acc[2][2];                   \
    wmma::fill_fragment(acc[0][0], 0.f); wmma::fill_fragment(acc[0][1], 0.f);        \
    wmma::fill_fragment(acc[1][0], 0.f); wmma::fill_fragment(acc[1][1], 0.f);        \
    for (int k0 = 0; k0 < (K_); k0 += 16) {                                          \
        const float* ap = (A_) + (size_t)(bm + r) * (lda_) + k0 + c8;                \
        *(float4*)&As[r * 16 + c8]     = *(const float4*)ap;                         \
        *(float4*)&As[r * 16 + c8 + 4] = *(const float4*)(ap + 4);                   \
        const float* wp = (W_) + (size_t)(bn + r) * (ldw_) + k0 + c8;                \
        *(float4*)&Bs[r * 16 + c8]     = *(const float4*)wp;                         \
        *(float4*)&Bs[r * 16 + c8 + 4] = *(const float4*)(wp + 4);                   \
        __syncthreads();                                                             \
        _Pragma("unroll")                                                            \
        for (int kk = 0; kk < 16; kk += 8) {                                         \
            wmma::fragment<wmma::matrix_a, 16, 16, 8, wmma::precision::tf32,         \
                           wmma::row_major> af[2];                                   \
            wmma::fragment<wmma::matrix_b, 16, 16, 8, wmma::precision::tf32,         \
                           wmma::col_major> bf[2];                                   \
            _Pragma("unroll")                                                        \
            for (int i = 0; i < 2; i++) {                                            \
                wmma::load_matrix_sync(af[i], &As[(wm + i * 16) * 16 + kk], 16);     \
                _Pragma("unroll")                                                    \
                for (int e = 0; e < af[i].num_elements; e++)                         \
                    af[i].x[e] = wmma::__float_to_tf32(af[i].x[e]);                  \
                wmma::load_matrix_sync(bf[i], &Bs[(wn + i * 16) * 16 + kk], 16);     \
                _Pragma("unroll")                                                    \
                for (int e = 0; e < bf[i].num_elements; e++)                         \
                    bf[i].x[e] = wmma::__float_to_tf32(bf[i].x[e]);                  \
            }                                                                        \
            _Pragma("unroll")                                                        \
            for (int i = 0; i < 2; i++)                                              \
                _Pragma("unroll")                                                    \
                for (int j = 0; j < 2; j++)                                          \
                    wmma::mma_sync(acc[i][j], af[i], bf[j], acc[i][j]);              \
        }                                                                            \
        __syncthreads();                                                             \
    }                                                                                \
    _Pragma("unroll")                                                                \
    for (int i = 0; i < 2; i++)                                                      \
        _Pragma("unroll")                                                            \
        for (int j = 0; j < 2; j++)                                                  \
            wmma::store_matrix_sync(&Cs[wm + i * 16][wn + j * 16], acc[i][j], 68,    \
                                    wmma::mem_row_major);                            \
    __syncthreads();

// ---------------------------------------------------------------------------
// Generic TF32 GEMM: C[M,N] = A[M,K] @ W[N,K]^T + bias, C in g_buf
// ---------------------------------------------------------------------------
__global__ __launch_bounds__(128) void k_gemm_tc(
    size_t a_off, int lda, const float* __restrict__ W, int ldw,
    const float* __restrict__ bias, size_t c_off, int ldc, int K)
{
    const float* A = g_buf + a_off;
    float* C = g_buf + c_off;
    __shared__ float As[64 * 16];
    __shared__ float Bs[64 * 16];
    __shared__ float Cs[64][68];
    int bm = blockIdx.y * 64, bn = blockIdx.x * 64;

    TC_MAINLOOP(A, lda, W, ldw, K)

    int r2 = t >> 1, h = (t & 1) * 32;
#pragma unroll
    for (int c = 0; c < 32; c += 4) {
        float4 v = *(float4*)&Cs[r2][h + c];
        float4 bv = *(const float4*)(bias + bn + h + c);
        v.x += bv.x; v.y += bv.y; v.z += bv.z; v.w += bv.w;
        *(float4*)(C + (size_t)(bm + r2) * ldc + bn + h + c) = v;
    }
}

// ---------------------------------------------------------------------------
// Logits GEMM (TF32 tensor core) with fused per-row (max, sumexp) partials.
// Grid (500, 32): 64 rows x 64 vocab cols per block. Never writes logits.
// ---------------------------------------------------------------------------
__global__ __launch_bounds__(128) void k_logits_tc(
    const float* __restrict__ W, const float* __restrict__ bias)
{
    const float* A = g_buf + OF_DOUT;
    __shared__ float As[64 * 16];
    __shared__ float Bs[64 * 16];
    __shared__ float Cs[64][68];
    __shared__ float bsh[64];
    int bm = blockIdx.y * 64, bn = blockIdx.x * 64;
    if (threadIdx.x < 64) bsh[threadIdx.x] = bias[bn + threadIdx.x];

    TC_MAINLOOP(A, 512, W, 512, 512)

    if (t < 64) {
        float m = -1e30f;
#pragma unroll 8
        for (int c = 0; c < 64; c++) m = fmaxf(m, Cs[t][c] + bsh[c]);
        float l = 0.f;
#pragma unroll 8
        for (int c = 0; c < 64; c++) l += __expf(Cs[t][c] + bsh[c] - m);
        size_t row = bm + t;
        g_buf[OF_LP + row * 1000 + (size_t)blockIdx.x * 2] = m;
        g_buf[OF_LP + row * 1000 + (size_t)blockIdx.x * 2 + 1] = l;
    }
}

// ---------------------------------------------------------------------------
// Encoder step: fused gh = h @ Whh^T, GRU cell, mask, write src_hidden.
// Grid 128 = dir(2) x colgroup(64, 8 h-cols each). 128 threads.
// h is double-buffered (pin = step parity).
// ---------------------------------------------------------------------------
__global__ __launch_bounds__(128) void k_enc_step(
    int s, const float* __restrict__ Whh_f, const float* __restrict__ bhh_f,
    const float* __restrict__ Whh_b, const float* __restrict__ bhh_b,
    const int* __restrict__ slen, int pin)
{
    int dir = blockIdx.x >> 6;
    int j0 = (blockIdx.x & 63) * 8;
    const float* Whh = dir ? Whh_b : Whh_f;
    const float* bhh = dir ? bhh_b : bhh_f;
    size_t hb = dir ? OF_HB : OF_HF;
    const float* hin = g_buf + hb + (size_t)pin * 16384;
    float* hout = g_buf + hb + (size_t)(pin ^ 1) * 16384;
    const float* gx = g_buf + (dir ? OF_GXB : OF_GXF);
    int tt = dir ? (63 - s) : s;

    __shared__ float Hs[32][68];
    __shared__ float Ws[24][68];
    int t = threadIdx.x;
    int rp = t >> 3;          // 0..15 -> rows rp, rp+16
    int j  = t & 7;
    float ar[2] = {0.f,0.f}, az[2] = {0.f,0.f}, an[2] = {0.f,0.f};
    int lrow = t >> 2, lkv = (t & 3) * 4;

    for (int k0 = 0; k0 < 512; k0 += 64) {
#pragma unroll
        for (int i = 0; i < 4; i++) {
            int kv = lkv + i;
            *(float4*)&Hs[lrow][kv*4] =
                *(const float4*)(hin + (size_t)lrow*512 + k0 + kv*4);
        }
#pragma unroll
        for (int i = 0; i < 3; i++) {
            int lin = t + 128*i;          // 0..383
            int wr = lin >> 4, kv = lin & 15;
            int g = wr >> 3, jj = wr & 7;
            *(float4*)&Ws[wr][kv*4] =
                *(const float4*)(Whh + (size_t)(g*512 + j0 + jj)*512 + k0 + kv*4);
        }
        __syncthreads();
#pragma unroll
        for (int kv = 0; kv < 16; kv++) {
            float4 h0 = *(const float4*)&Hs[rp][kv*4];
            float4 h1 = *(const float4*)&Hs[rp+16][kv*4];
            float4 wrv = *(const float4*)&Ws[j][kv*4];
            float4 wzv = *(const float4*)&Ws[8+j][kv*4];
            float4 wnv = *(const float4*)&Ws[16+j][kv*4];
            ar[0] = dot4(h0, wrv, ar[0]); ar[1] = dot4(h1, wrv, ar[1]);
            az[0] = dot4(h0, wzv, az[0]); az[1] = dot4(h1, wzv, az[1]);
            an[0] = dot4(h0, wnv, an[0]); an[1] = dot4(h1, wnv, an[1]);
        }
        __syncthreads();
    }
    int jg = j0 + j;
    float br = bhh[jg], bz = bhh[512+jg], bn = bhh[1024+jg];
#pragma unroll
    for (int q = 0; q < 2; q++) {
        int r = rp + q*16;                 // batch index
        size_t grow = (size_t)r*64 + tt;
        float gxr = gx[grow*1536 + jg];
        float gxz = gx[grow*1536 + 512 + jg];
        float gxn = gx[grow*1536 + 1024 + jg];
        float rr = sigm(gxr + ar[q] + br);
        float zz = sigm(gxz + az[q] + bz);
        float nn = tanhf(gxn + rr * (an[q] + bn));
        float hold = hin[(size_t)r*512 + jg];
        float hnew = (1.f - zz) * nn + zz * hold;
        bool m = tt < slen[r];
        hout[(size_t)r*512 + jg] = m ? hnew : hold;
        g_buf[OF_SRCH + grow*1024 + (size_t)dir*512 + jg] = m ? hnew : 0.f;
    }
}

// ---------------------------------------------------------------------------
// Decoder attention (one block per batch row): q = A_W@h + A_b;
// e[s] = A_v . tanh(Uh[b,s] + q) + knockout; alpha = softmax; ctx = alpha.H
// ---------------------------------------------------------------------------
__global__ __launch_bounds__(256) void k_attn(
    const float* __restrict__ A_W, const float* __restrict__ A_b,
    const float* __restrict__ A_v, const int* __restrict__ slen, int pin)
{
    int b = blockIdx.x;
    int t = threadIdx.x;
    __shared__ float hs[512], qs[512], av[512], es[64];
    const float* hin = g_buf + OF_HD + (size_t)pin*16384 + (size_t)b*512;
    hs[t] = hin[t]; hs[t+256] = hin[t+256];
    av[t] = A_v[t]; av[t+256] = A_v[t+256];
    __syncthreads();
#pragma unroll
    for (int jj = 0; jj < 2; jj++) {
        int jq = t + jj*256;
        const float* wrow = A_W + (size_t)jq*512;
        float acc = A_b[jq];
        for (int k = 0; k < 512; k += 4)
            acc = dot4(*(const float4*)(wrow + k), *(const float4*)&hs[k], acc);
        qs[jq] = acc;
    }
    __syncthreads();
    int w = t >> 5, lane = t & 31;
    int sl = slen[b];
#pragma unroll
    for (int si = 0; si < 8; si++) {
        int s = w*8 + si;
        const float* uh = g_buf + OF_UH + ((size_t)b*64 + s)*512;
        float acc = 0.f;
        for (int jq = lane; jq < 512; jq += 32)
            acc = fmaf(av[jq], tanhf(uh[jq] + qs[jq]), acc);
#pragma unroll
        for (int o = 16; o > 0; o >>= 1) acc += __shfl_xor_sync(0xffffffffu, acc, o);
        if (lane == 0) es[s] = (s < sl) ? acc : acc - 1e9f;
    }
    __syncthreads();
    if (t < 32) {
        float a0 = es[t], a1 = es[t+32];
        float m = fmaxf(a0, a1);
#pragma unroll
        for (int o = 16; o > 0; o >>= 1) m = fmaxf(m, __shfl_xor_sync(0xffffffffu, m, o));
        float e0 = __expf(a0 - m), e1 = __expf(a1 - m);
        float sum = e0 + e1;
#pragma unroll
        for (int o = 16; o > 0; o >>= 1) sum += __shfl_xor_sync(0xffffffffu, sum, o);
        es[t] = e0 / sum; es[t+32] = e1 / sum;
    }
    __syncthreads();
#pragma unroll
    for (int dd = 0; dd < 4; dd++) {
        int d = t + dd*256;
        const float* sh = g_buf + OF_SRCH + (size_t)b*64*1024 + d;
        float acc = 0.f;
        for (int s = 0; s < 64; s++)
            acc = fmaf(es[s], sh[(size_t)s*1024], acc);
        g_buf[OF_CTX + (size_t)b*1024 + d] = acc;
    }
}

// ---------------------------------------------------------------------------
// Decoder gate GEMM (split-K): gh = [ctx ; h] @ [Wih[:,512:] ; Whh]^T
// grid (24 colblocks x 6 kchunks of 256), 256 threads.
// ---------------------------------------------------------------------------
__global__ __launch_bounds__(256) void k_dec_gemm(
    const float* __restrict__ Wih, const float* __restrict__ Whh, int pin)
{
    int n0 = blockIdx.x * 64;
    int kc = blockIdx.y;
    const float* A; int lda; const float* W; int ldw; int woff; int kbase;
    if (kc < 4) { A = g_buf + OF_CTX; lda = 1024; W = Wih; ldw = 1536; woff = 512; kbase = kc*256; }
    else { A = g_buf + OF_HD + (size_t)pin*16384; lda = 512; W = Whh; ldw = 512; woff = 0; kbase = (kc-4)*256; }

    __shared__ float Hs[64][33];
    __shared__ float Ws2[64][68];
    int t = threadIdx.x;
    int w = t >> 5, lane = t & 31;
    float acc[8] = {};

    for (int k0 = 0; k0 < 256; k0 += 64) {
#pragma unroll
        for (int i = 0; i < 2; i++) {
            int vec = t + 256*i;           // 0..511
            int r = vec >> 4, kv = vec & 15;
            float4 a = *(const float4*)(A + (size_t)r*lda + kbase + k0 + kv*4);
            Hs[kv*4+0][r]=a.x; Hs[kv*4+1][r]=a.y; Hs[kv*4+2][r]=a.z; Hs[kv*4+3][r]=a.w;
        }
#pragma unroll
        for (int i = 0; i < 4; i++) {
            int vec = t + 256*i;           // 0..1023
            int nl = vec >> 4, kv = vec & 15;
            float4 wv = *(const float4*)(W + (size_t)(n0+nl)*ldw + woff + kbase + k0 + kv*4);
            Ws2[kv*4+0][nl]=wv.x; Ws2[kv*4+1][nl]=wv.y; Ws2[kv*4+2][nl]=wv.z; Ws2[kv*4+3][nl]=wv.w;
        }
        __syncthreads();
#pragma unroll
        for (int k = 0; k < 64; k++) {
            float hv = Hs[k][lane];
            float4 w0 = *(const float4*)&Ws2[k][w*8];
            float4 w1 = *(const float4*)&Ws2[k][w*8+4];
            acc[0]=fmaf(hv,w0.x,acc[0]); acc[1]=fmaf(hv,w0.y,acc[1]);
            acc[2]=fmaf(hv,w0.z,acc[2]); acc[3]=fmaf(hv,w0.w,acc[3]);
            acc[4]=fmaf(hv,w1.x,acc[4]); acc[5]=fmaf(hv,w1.y,acc[5]);
            acc[6]=fmaf(hv,w1.z,acc[6]); acc[7]=fmaf(hv,w1.w,acc[7]);
        }
        __syncthreads();
    }
    float* part = g_buf + OF_PART + (size_t)kc*49152 + (size_t)lane*1536 + n0 + w*8;
#pragma unroll
    for (int c = 0; c < 8; c++) part[c] = acc[c];
}

// ---------------------------------------------------------------------------
// Decoder pointwise GRU: combine split-K partials + dgx, update h, write dec_out
// ---------------------------------------------------------------------------
__global__ void k_dec_point(int i, const float* __restrict__ bhh,
                            const int* __restrict__ tlen, int pin)
{
    int b = blockIdx.x;
    int j = threadIdx.x;          // 512
    float gr = 0.f, gz = 0.f, gn = 0.f;
#pragma unroll
    for (int kc = 0; kc < 6; kc++) {
        const float* p = g_buf + OF_PART + (size_t)kc*49152 + (size_t)b*1536;
        gr += p[j]; gz += p[512+j]; gn += p[1024+j];
    }
    const float* hin = g_buf + OF_HD + (size_t)pin*16384;
    float* hout = g_buf + OF_HD + (size_t)(pin^1)*16384;
    size_t grow = (size_t)b*64 + i;
    const float* gx = g_buf + OF_DGX + grow*1536;
    float rr = sigm(gx[j] + gr + bhh[j]);
    float zz = sigm(gx[512+j] + gz + bhh[512+j]);
    float nn = tanhf(gx[1024+j] + rr*(gn + bhh[1024+j]));
    float hold = hin[(size_t)b*512 + j];
    float hnew = (1.f - zz)*nn + zz*hold;
    bool m = i < tlen[b];
    hout[(size_t)b*512 + j] = m ? hnew : hold;
    g_buf[OF_DOUT + grow*512 + j] = m ? hnew : 0.f;
}

// ---------------------------------------------------------------------------
// Per-row: combine 500 (m,l) partials -> logZ; picked logit via dot; contrib
// ---------------------------------------------------------------------------
__global__ __launch_bounds__(256) void k_combine(
    const int* __restrict__ tgt, const float* __restrict__ out_w,
    const float* __restrict__ out_b)
{
    int row = blockIdx.x * 8 + (threadIdx.x >> 5);
    int lane = threadIdx.x & 31;
    const float* p = g_buf + OF_LP + (size_t)row*1000;
    float M = -1e30f;
    for (int c = lane; c < 500; c += 32) M = fmaxf(M, p[c*2]);
#pragma unroll
    for (int o = 16; o > 0; o >>= 1) M = fmaxf(M, __shfl_xor_sync(0xffffffffu, M, o));
    float L = 0.f;
    for (int c = lane; c < 500; c += 32) L += p[c*2+1] * __expf(p[c*2] - M);
#pragma unroll
    for (int o = 16; o > 0; o >>= 1) L += __shfl_xor_sync(0xffffffffu, L, o);
    int b = row >> 6, tc = row & 63;
    int goal = (tc < 63) ? tgt[b*64 + tc + 1] : 0;
    float contrib = 0.f, cnt = 0.f;
    if (goal != 0) {
        const float* x = g_buf + OF_DOUT + (size_t)row*512;
        const float* wrow = out_w + (size_t)goal*512;
        float d = 0.f;
        for (int k = lane; k < 512; k += 32) d = fmaf(x[k], wrow[k], d);
#pragma unroll
        for (int o = 16; o > 0; o >>= 1) d += __shfl_xor_sync(0xffffffffu, d, o);
        contrib = (d + out_b[goal]) - (M + logf(L));
        cnt = 1.f;
    }
    if (lane == 0) {
        g_buf[OF_CON + row] = contrib;
        g_buf[OF_CNT + row] = cnt;
    }
}

// ---------------------------------------------------------------------------
// Final deterministic reduce -> loss
// ---------------------------------------------------------------------------
__global__ void k_final(float* out) {
    __shared__ float sc[1024], sn[1024];
    int t = threadIdx.x;
    sc[t] = g_buf[OF_CON + t] + g_buf[OF_CON + 1024 + t];
    sn[t] = g_buf[OF_CNT + t] + g_buf[OF_CNT + 1024 + t];
    __syncthreads();
    for (int o = 512; o > 0; o >>= 1) {
        if (t < o) { sc[t] += sc[t+o]; sn[t] += sn[t+o]; }
        __syncthreads();
    }
    if (t == 0) out[0] = -sc[0] / sn[0];
}

// ---------------------------------------------------------------------------
// Host orchestration (graph-capturable: kernel launches only, default stream)
// ---------------------------------------------------------------------------
extern "C" void kernel_launch(void* const* d_in, const int* in_sizes, int n_in,
                              void* d_out, int out_size)
{
    const int*   src_seqs = (const int*)  d_in[0];
    const int*   src_len  = (const int*)  d_in[1];
    const int*   tgt_seqs = (const int*)  d_in[2];
    const int*   tgt_len  = (const int*)  d_in[3];
    const float* src_emb  = (const float*)d_in[4];
    const float* eWih_f   = (const float*)d_in[5];
    const float* eWhh_f   = (const float*)d_in[6];
    const float* ebih_f   = (const float*)d_in[7];
    const float* ebhh_f   = (const float*)d_in[8];
    const float* eWih_b   = (const float*)d_in[9];
    const float* eWhh_b   = (const float*)d_in[10];
    const float* ebih_b   = (const float*)d_in[11];
    const float* ebhh_b   = (const float*)d_in[12];
    const float* tgt_emb  = (const float*)d_in[13];
    const float* dWih     = (const float*)d_in[14];
    const float* dWhh     = (const float*)d_in[15];
    const float* dbih     = (const float*)d_in[16];
    const float* dbhh     = (const float*)d_in[17];
    const float* U_w      = (const float*)d_in[18];
    const float* U_b      = (const float*)d_in[19];
    const float* A_W      = (const float*)d_in[20];
    const float* A_b      = (const float*)d_in[21];
    const float* A_v      = (const float*)d_in[22];
    const float* out_w    = (const float*)d_in[23];
    const float* out_b    = (const float*)d_in[24];

    k_zero<<<64, 256>>>();
    k_embed<<<2048, 128>>>(src_seqs, src_emb, OF_ESRC);
    k_embed<<<2048, 128>>>(tgt_seqs, tgt_emb, OF_ETGT);

    // input-gate pre-GEMMs (bias = bih folded in), TF32 tensor cores
    k_gemm_tc<<<dim3(24, 32), 128>>>(OF_ESRC, 512, eWih_f, 512, ebih_f, OF_GXF, 1536, 512);
    k_gemm_tc<<<dim3(24, 32), 128>>>(OF_ESRC, 512, eWih_b, 512, ebih_b, OF_GXB, 1536, 512);
    k_gemm_tc<<<dim3(24, 32), 128>>>(OF_ETGT, 512, dWih, 1536, dbih, OF_DGX, 1536, 512);

    for (int s = 0; s < 64; s++)
        k_enc_step<<<128, 128>>>(s, eWhh_f, ebhh_f, eWhh_b, ebhh_b, src_len, s & 1);

    k_gemm_tc<<<dim3(8, 32), 128>>>(OF_SRCH, 1024, U_w, 1024, U_b, OF_UH, 512, 1024);

    for (int i = 0; i < 64; i++) {
        k_attn<<<32, 256>>>(A_W, A_b, A_v, src_len, i & 1);
        k_dec_gemm<<<dim3(24, 6), 256>>>(dWih, dWhh, i & 1);
        k_dec_point<<<32, 512>>>(i, dbhh, tgt_len, i & 1);
    }

    k_logits_tc<<<dim3(500, 32), 128>>>(out_w, out_b);
    k_combine<<<256, 256>>>(tgt_seqs, out_w, out_b);
    k_final<<<1, 1024>>>((float*)d_out);
}

// round 7
// speedup vs baseline: 1.1035x; 1.1035x over previous
#include <cuda_runtime.h>
#include <mma.h>
#include <math.h>

using namespace nvcuda;

// ---------------------------------------------------------------------------
// Problem constants: B=32, S=T=64, E=H=512, G=3H=1536, V=32000
// ---------------------------------------------------------------------------

// Scratch offsets (in floats) into one big __device__ buffer
#define OF_ESRC 0ul            /* 2048*512  */
#define OF_ETGT 1048576ul      /* 2048*512  */
#define OF_GXF  2097152ul      /* 2048*1536 */
#define OF_GXB  5242880ul      /* 2048*1536 */
#define OF_DGX  8388608ul      /* 2048*1536 */
#define OF_SRCH 11534336ul     /* 2048*1024 */
#define OF_UH   13631488ul     /* 2048*512  */
#define OF_DOUT 14680064ul     /* 2048*512  */
#define OF_HF   15728640ul     /* 2*32*512 double buffer */
#define OF_HB   15761408ul     /* 2*32*512 */
#define OF_HD   15794176ul     /* 2*32*512 */
#define OF_CTX  15826944ul     /* 32*1536 gx_ctx (alpha @ P) */
#define OF_LP   15876096ul     /* 2048*250*2 logits (max,sumexp) partials */
#define OF_CON  16900096ul     /* 2048 */
#define OF_CNT  16902144ul     /* 2048 */
#define OF_P    16904192ul     /* 2048*1536 : P = src_hidden @ Wih_ctx^T */
#define BUF_TOTAL 20049920ul

__device__ __align__(16) float g_buf[BUF_TOTAL];

__device__ __forceinline__ float sigm(float x) { return 1.f / (1.f + __expf(-x)); }
__device__ __forceinline__ float dot4(float4 a, float4 b, float acc) {
    acc = fmaf(a.x, b.x, acc); acc = fmaf(a.y, b.y, acc);
    acc = fmaf(a.z, b.z, acc); acc = fmaf(a.w, b.w, acc);
    return acc;
}
__device__ __forceinline__ float T32(float x) { return wmma::__float_to_tf32(x); }

// ---------------------------------------------------------------------------
// zero initial hidden states (runs every replay)
// ---------------------------------------------------------------------------
__global__ void k_zero() {
    int i = blockIdx.x * 256 + threadIdx.x;   // grid 64 -> 16384
    g_buf[OF_HF + i] = 0.f;
    g_buf[OF_HB + i] = 0.f;
    g_buf[OF_HD + i] = 0.f;
}

// ---------------------------------------------------------------------------
// embedding gather: row r -> table[ids[r]] (512 floats)
// ---------------------------------------------------------------------------
__global__ void k_embed(const int* __restrict__ ids, const float* __restrict__ tab,
                        size_t out_off) {
    int row = blockIdx.x;
    const float4* src = (const float4*)(tab + (size_t)ids[row] * 512);
    float4* dst = (float4*)(g_buf + out_off + (size_t)row * 512);
    dst[threadIdx.x] = src[threadIdx.x];
}

// ---------------------------------------------------------------------------
// TF32 GEMM, BM=64 x BN=128 x BK=16, 256 threads (8 warps, 2x4, 32x32/warp).
// Double-buffered smem, padded stride 20, tf32 rounding at smem-store time.
// C[M,N] = A[M,K] @ W[N,K]^T (+bias). A,C in g_buf; W in global.
// logits_mode: instead of storing C, emit per-row (max, sumexp) partials.
// ---------------------------------------------------------------------------
__global__ __launch_bounds__(256) void k_gemm128(
    size_t a_off, int lda, const float* __restrict__ W, int ldw,
    const float* __restrict__ bias, size_t c_off, int ldc, int K,
    int logits_mode)
{
    __shared__ float sm[8704];   // mainloop: 2 bufs x (64*20 + 128*20) = 7680
                                 // epilogue: Cs[64][136] = 8704
    const float* A = g_buf + a_off;
    int bm = blockIdx.y * 64, bn = blockIdx.x * 128;
    int t = threadIdx.x;
    int wid = t >> 5;
    int wm = (wid >> 2) * 32, wn = (wid & 3) * 32;
    int ar = t >> 2, ac = (t & 3) * 4;       // A loader: (64 x 16), 1 float4/thr
    int br = ar, bc = ac;                    // B loader: rows br, br+64

    wmma::fragment<wmma::accumulator, 16, 16, 8, float> acc[2][2];
#pragma unroll
    for (int i = 0; i < 2; i++)
#pragma unroll
        for (int j = 0; j < 2; j++) wmma::fill_fragment(acc[i][j], 0.f);

    // prologue: load k0 = 0 into buf 0
    {
        float4 a  = *(const float4*)(A + (size_t)(bm + ar) * lda + ac);
        float4 b0 = *(const float4*)(W + (size_t)(bn + br) * ldw + bc);
        float4 b1 = *(const float4*)(W + (size_t)(bn + br + 64) * ldw + bc);
        float* As = sm; float* Bs = sm + 1280;
        As[ar*20+ac+0]=T32(a.x);  As[ar*20+ac+1]=T32(a.y);
        As[ar*20+ac+2]=T32(a.z);  As[ar*20+ac+3]=T32(a.w);
        Bs[br*20+bc+0]=T32(b0.x); Bs[br*20+bc+1]=T32(b0.y);
        Bs[br*20+bc+2]=T32(b0.z); Bs[br*20+bc+3]=T32(b0.w);
        Bs[(br+64)*20+bc+0]=T32(b1.x); Bs[(br+64)*20+bc+1]=T32(b1.y);
        Bs[(br+64)*20+bc+2]=T32(b1.z); Bs[(br+64)*20+bc+3]=T32(b1.w);
    }
    __syncthreads();

    int buf = 0;
    for (int k0 = 0; k0 < K; k0 += 16) {
        float4 pa, pb0, pb1;
        bool more = (k0 + 16) < K;
        if (more) {
            pa  = *(const float4*)(A + (size_t)(bm + ar) * lda + k0 + 16 + ac);
            pb0 = *(const float4*)(W + (size_t)(bn + br) * ldw + k0 + 16 + bc);
            pb1 = *(const float4*)(W + (size_t)(bn + br + 64) * ldw + k0 + 16 + bc);
        }
        const float* As = sm + buf * 3840;
        const float* Bs = As + 1280;
#pragma unroll
        for (int kk = 0; kk < 16; kk += 8) {
            wmma::fragment<wmma::matrix_a, 16, 16, 8, wmma::precision::tf32,
                           wmma::row_major> af[2];
            wmma::fragment<wmma::matrix_b, 16, 16, 8, wmma::precision::tf32,
                           wmma::col_major> bf[2];
            wmma::load_matrix_sync(af[0], As + (wm +  0) * 20 + kk, 20);
            wmma::load_matrix_sync(af[1], As + (wm + 16) * 20 + kk, 20);
            wmma::load_matrix_sync(bf[0], Bs + (wn +  0) * 20 + kk, 20);
            wmma::load_matrix_sync(bf[1], Bs + (wn + 16) * 20 + kk, 20);
            wmma::mma_sync(acc[0][0], af[0], bf[0], acc[0][0]);
            wmma::mma_sync(acc[0][1], af[0], bf[1], acc[0][1]);
            wmma::mma_sync(acc[1][0], af[1], bf[0], acc[1][0]);
            wmma::mma_sync(acc[1][1], af[1], bf[1], acc[1][1]);
        }
        if (more) {
            float* Ad = sm + (buf ^ 1) * 3840;
            float* Bd = Ad + 1280;
            Ad[ar*20+ac+0]=T32(pa.x);  Ad[ar*20+ac+1]=T32(pa.y);
            Ad[ar*20+ac+2]=T32(pa.z);  Ad[ar*20+ac+3]=T32(pa.w);
            Bd[br*20+bc+0]=T32(pb0.x); Bd[br*20+bc+1]=T32(pb0.y);
            Bd[br*20+bc+2]=T32(pb0.z); Bd[br*20+bc+3]=T32(pb0.w);
            Bd[(br+64)*20+bc+0]=T32(pb1.x); Bd[(br+64)*20+bc+1]=T32(pb1.y);
            Bd[(br+64)*20+bc+2]=T32(pb1.z); Bd[(br+64)*20+bc+3]=T32(pb1.w);
        }
        __syncthreads();
        buf ^= 1;
    }

    // epilogue: park C tile in smem (reuse), then bias + store or logsumexp
    float* Cs = sm;
#pragma unroll
    for (int i = 0; i < 2; i++)
#pragma unroll
        for (int j = 0; j < 2; j++)
            wmma::store_matrix_sync(Cs + (wm + i*16) * 136 + wn + j*16,
                                    acc[i][j], 136, wmma::mem_row_major);
    __syncthreads();

    int r2 = t >> 2, c0 = (t & 3) * 32;
    if (!logits_mode) {
        float* C = g_buf + c_off;
#pragma unroll
        for (int c = 0; c < 32; c += 4) {
            float4 v = *(float4*)(Cs + r2 * 136 + c0 + c);
            if (bias) {
                float4 bv = *(const float4*)(bias + bn + c0 + c);
                v.x += bv.x; v.y += bv.y; v.z += bv.z; v.w += bv.w;
            }
            *(float4*)(C + (size_t)(bm + r2) * ldc + bn + c0 + c) = v;
        }
    } else {
        float vals[32];
        float m = -1e30f;
#pragma unroll
        for (int c = 0; c < 32; c++) {
            float v = Cs[r2 * 136 + c0 + c] + bias[bn + c0 + c];
            vals[c] = v; m = fmaxf(m, v);
        }
        m = fmaxf(m, __shfl_xor_sync(0xffffffffu, m, 1));
        m = fmaxf(m, __shfl_xor_sync(0xffffffffu, m, 2));
        float l = 0.f;
#pragma unroll
        for (int c = 0; c < 32; c++) l += __expf(vals[c] - m);
        l += __shfl_xor_sync(0xffffffffu, l, 1);
        l += __shfl_xor_sync(0xffffffffu, l, 2);
        if ((t & 3) == 0) {
            size_t row = bm + r2;
            g_buf[OF_LP + row * 500 + (size_t)blockIdx.x * 2]     = m;
            g_buf[OF_LP + row * 500 + (size_t)blockIdx.x * 2 + 1] = l;
        }
    }
}

// ---------------------------------------------------------------------------
// Encoder step: fused gh = h @ Whh^T, GRU cell, mask, write src_hidden.
// Grid 128 = dir(2) x colgroup(64, 8 h-cols each). 128 threads.
// ---------------------------------------------------------------------------
__global__ __launch_bounds__(128) void k_enc_step(
    int s, const float* __restrict__ Whh_f, const float* __restrict__ bhh_f,
    const float* __restrict__ Whh_b, const float* __restrict__ bhh_b,
    const int* __restrict__ slen, int pin)
{
    int dir = blockIdx.x >> 6;
    int j0 = (blockIdx.x & 63) * 8;
    const float* Whh = dir ? Whh_b : Whh_f;
    const float* bhh = dir ? bhh_b : bhh_f;
    size_t hb = dir ? OF_HB : OF_HF;
    const float* hin = g_buf + hb + (size_t)pin * 16384;
    float* hout = g_buf + hb + (size_t)(pin ^ 1) * 16384;
    const float* gx = g_buf + (dir ? OF_GXB : OF_GXF);
    int tt = dir ? (63 - s) : s;

    __shared__ float Hs[32][68];
    __shared__ float Ws[24][68];
    int t = threadIdx.x;
    int rp = t >> 3;          // 0..15 -> rows rp, rp+16
    int j  = t & 7;
    float ar[2] = {0.f,0.f}, az[2] = {0.f,0.f}, an[2] = {0.f,0.f};
    int lrow = t >> 2, lkv = (t & 3) * 4;

    for (int k0 = 0; k0 < 512; k0 += 64) {
#pragma unroll
        for (int i = 0; i < 4; i++) {
            int kv = lkv + i;
            *(float4*)&Hs[lrow][kv*4] =
                *(const float4*)(hin + (size_t)lrow*512 + k0 + kv*4);
        }
#pragma unroll
        for (int i = 0; i < 3; i++) {
            int lin = t + 128*i;          // 0..383
            int wr = lin >> 4, kv = lin & 15;
            int g = wr >> 3, jj = wr & 7;
            *(float4*)&Ws[wr][kv*4] =
                *(const float4*)(Whh + (size_t)(g*512 + j0 + jj)*512 + k0 + kv*4);
        }
        __syncthreads();
#pragma unroll
        for (int kv = 0; kv < 16; kv++) {
            float4 h0 = *(const float4*)&Hs[rp][kv*4];
            float4 h1 = *(const float4*)&Hs[rp+16][kv*4];
            float4 wrv = *(const float4*)&Ws[j][kv*4];
            float4 wzv = *(const float4*)&Ws[8+j][kv*4];
            float4 wnv = *(const float4*)&Ws[16+j][kv*4];
            ar[0] = dot4(h0, wrv, ar[0]); ar[1] = dot4(h1, wrv, ar[1]);
            az[0] = dot4(h0, wzv, az[0]); az[1] = dot4(h1, wzv, az[1]);
            an[0] = dot4(h0, wnv, an[0]); an[1] = dot4(h1, wnv, an[1]);
        }
        __syncthreads();
    }
    int jg = j0 + j;
    float br = bhh[jg], bz = bhh[512+jg], bn = bhh[1024+jg];
#pragma unroll
    for (int q = 0; q < 2; q++) {
        int r = rp + q*16;                 // batch index
        size_t grow = (size_t)r*64 + tt;
        float gxr = gx[grow*1536 + jg];
        float gxz = gx[grow*1536 + 512 + jg];
        float gxn = gx[grow*1536 + 1024 + jg];
        float rr = sigm(gxr + ar[q] + br);
        float zz = sigm(gxz + az[q] + bz);
        float nn = tanhf(gxn + rr * (an[q] + bn));
        float hold = hin[(size_t)r*512 + jg];
        float hnew = (1.f - zz) * nn + zz * hold;
        bool m = tt < slen[r];
        hout[(size_t)r*512 + jg] = m ? hnew : hold;
        g_buf[OF_SRCH + grow*1024 + (size_t)dir*512 + jg] = m ? hnew : 0.f;
    }
}

// ---------------------------------------------------------------------------
// Decoder attention (one block per batch row): q = A_W@h + A_b;
// e[s] = A_v . tanh(Uh[b,s] + q) + knockout; alpha = softmax;
// gx_ctx = alpha @ P[b]   (P = src_hidden @ Wih_ctx^T, precomputed)
// ---------------------------------------------------------------------------
__global__ __launch_bounds__(256) void k_attn(
    const float* __restrict__ A_W, const float* __restrict__ A_b,
    const float* __restrict__ A_v, const int* __restrict__ slen, int pin)
{
    int b = blockIdx.x;
    int t = threadIdx.x;
    __shared__ float hs[512], qs[512], av[512], es[64];
    const float* hin = g_buf + OF_HD + (size_t)pin*16384 + (size_t)b*512;
    hs[t] = hin[t]; hs[t+256] = hin[t+256];
    av[t] = A_v[t]; av[t+256] = A_v[t+256];
    __syncthreads();
#pragma unroll
    for (int jj = 0; jj < 2; jj++) {
        int jq = t + jj*256;
        const float* wrow = A_W + (size_t)jq*512;
        float acc = A_b[jq];
        for (int k = 0; k < 512; k += 4)
            acc = dot4(*(const float4*)(wrow + k), *(const float4*)&hs[k], acc);
        qs[jq] = acc;
    }
    __syncthreads();
    int w = t >> 5, lane = t & 31;
    int sl = slen[b];
#pragma unroll
    for (int si = 0; si < 8; si++) {
        int s = w*8 + si;
        const float* uh = g_buf + OF_UH + ((size_t)b*64 + s)*512;
        float acc = 0.f;
        for (int jq = lane; jq < 512; jq += 32)
            acc = fmaf(av[jq], tanhf(uh[jq] + qs[jq]), acc);
#pragma unroll
        for (int o = 16; o > 0; o >>= 1) acc += __shfl_xor_sync(0xffffffffu, acc, o);
        if (lane == 0) es[s] = (s < sl) ? acc : acc - 1e9f;
    }
    __syncthreads();
    if (t < 32) {
        float a0 = es[t], a1 = es[t+32];
        float m = fmaxf(a0, a1);
#pragma unroll
        for (int o = 16; o > 0; o >>= 1) m = fmaxf(m, __shfl_xor_sync(0xffffffffu, m, o));
        float e0 = __expf(a0 - m), e1 = __expf(a1 - m);
        float sum = e0 + e1;
#pragma unroll
        for (int o = 16; o > 0; o >>= 1) sum += __shfl_xor_sync(0xffffffffu, sum, o);
        es[t] = e0 / sum; es[t+32] = e1 / sum;
    }
    __syncthreads();
    // gx_ctx[b, 0:1536] = sum_s alpha[s] * P[b, s, :]
    const float* Pb = g_buf + OF_P + (size_t)b * 64 * 1536;
#pragma unroll
    for (int dd = 0; dd < 6; dd++) {
        int d = t + dd * 256;
        float acc = 0.f;
#pragma unroll 8
        for (int s = 0; s < 64; s++)
            acc = fmaf(es[s], Pb[(size_t)s*1536 + d], acc);
        g_buf[OF_CTX + (size_t)b*1536 + d] = acc;
    }
}

// ---------------------------------------------------------------------------
// Decoder step: gh = h @ Whh^T, GRU cell with gx = dgx[t] + gx_ctx, mask,
// write dec_out. Grid 64 colgroups x 128 threads (encoder-style).
// ---------------------------------------------------------------------------
__global__ __launch_bounds__(128) void k_dec_step(
    int step, const float* __restrict__ Whh, const float* __restrict__ bhh,
    const int* __restrict__ tlen, int pin)
{
    int j0 = blockIdx.x * 8;
    const float* hin = g_buf + OF_HD + (size_t)pin * 16384;
    float* hout = g_buf + OF_HD + (size_t)(pin ^ 1) * 16384;

    __shared__ float Hs[32][68];
    __shared__ float Ws[24][68];
    int t = threadIdx.x;
    int rp = t >> 3;
    int j  = t & 7;
    float ar[2] = {0.f,0.f}, az[2] = {0.f,0.f}, an[2] = {0.f,0.f};
    int lrow = t >> 2, lkv = (t & 3) * 4;

    for (int k0 = 0; k0 < 512; k0 += 64) {
#pragma unroll
        for (int i = 0; i < 4; i++) {
            int kv = lkv + i;
            *(float4*)&Hs[lrow][kv*4] =
                *(const float4*)(hin + (size_t)lrow*512 + k0 + kv*4);
        }
#pragma unroll
        for (int i = 0; i < 3; i++) {
            int lin = t + 128*i;
            int wr = lin >> 4, kv = lin & 15;
            int g = wr >> 3, jj = wr & 7;
            *(float4*)&Ws[wr][kv*4] =
                *(const float4*)(Whh + (size_t)(g*512 + j0 + jj)*512 + k0 + kv*4);
        }
        __syncthreads();
#pragma unroll
        for (int kv = 0; kv < 16; kv++) {
            float4 h0 = *(const float4*)&Hs[rp][kv*4];
            float4 h1 = *(const float4*)&Hs[rp+16][kv*4];
            float4 wrv = *(const float4*)&Ws[j][kv*4];
            float4 wzv = *(const float4*)&Ws[8+j][kv*4];
            float4 wnv = *(const float4*)&Ws[16+j][kv*4];
            ar[0] = dot4(h0, wrv, ar[0]); ar[1] = dot4(h1, wrv, ar[1]);
            az[0] = dot4(h0, wzv, az[0]); az[1] = dot4(h1, wzv, az[1]);
            an[0] = dot4(h0, wnv, an[0]); an[1] = dot4(h1, wnv, an[1]);
        }
        __syncthreads();
    }
    int jg = j0 + j;
    float br = bhh[jg], bz = bhh[512+jg], bn = bhh[1024+jg];
#pragma unroll
    for (int q = 0; q < 2; q++) {
        int r = rp + q*16;
        size_t grow = (size_t)r*64 + step;
        const float* gx = g_buf + OF_DGX + grow*1536;
        const float* gc = g_buf + OF_CTX + (size_t)r*1536;
        float gxr = gx[jg]        + gc[jg];
        float gxz = gx[512 + jg]  + gc[512 + jg];
        float gxn = gx[1024 + jg] + gc[1024 + jg];
        float rr = sigm(gxr + ar[q] + br);
        float zz = sigm(gxz + az[q] + bz);
        float nn = tanhf(gxn + rr * (an[q] + bn));
        float hold = hin[(size_t)r*512 + jg];
        float hnew = (1.f - zz) * nn + zz * hold;
        bool m = step < tlen[r];
        hout[(size_t)r*512 + jg] = m ? hnew : hold;
        g_buf[OF_DOUT + grow*512 + jg] = m ? hnew : 0.f;
    }
}

// ---------------------------------------------------------------------------
// Per-row: combine 250 (m,l) partials -> logZ; picked logit via dot; contrib
// ---------------------------------------------------------------------------
__global__ __launch_bounds__(256) void k_combine(
    const int* __restrict__ tgt, const float* __restrict__ out_w,
    const float* __restrict__ out_b)
{
    int row = blockIdx.x * 8 + (threadIdx.x >> 5);
    int lane = threadIdx.x & 31;
    const float* p = g_buf + OF_LP + (size_t)row*500;
    float M = -1e30f;
    for (int c = lane; c < 250; c += 32) M = fmaxf(M, p[c*2]);
#pragma unroll
    for (int o = 16; o > 0; o >>= 1) M = fmaxf(M, __shfl_xor_sync(0xffffffffu, M, o));
    float L = 0.f;
    for (int c = lane; c < 250; c += 32) L += p[c*2+1] * __expf(p[c*2] - M);
#pragma unroll
    for (int o = 16; o > 0; o >>= 1) L += __shfl_xor_sync(0xffffffffu, L, o);
    int b = row >> 6, tc = row & 63;
    int goal = (tc < 63) ? tgt[b*64 + tc + 1] : 0;
    float contrib = 0.f, cnt = 0.f;
    if (goal != 0) {
        const float* x = g_buf + OF_DOUT + (size_t)row*512;
        const float* wrow = out_w + (size_t)goal*512;
        float d = 0.f;
        for (int k = lane; k < 512; k += 32) d = fmaf(x[k], wrow[k], d);
#pragma unroll
        for (int o = 16; o > 0; o >>= 1) d += __shfl_xor_sync(0xffffffffu, d, o);
        contrib = (d + out_b[goal]) - (M + logf(L));
        cnt = 1.f;
    }
    if (lane == 0) {
        g_buf[OF_CON + row] = contrib;
        g_buf[OF_CNT + row] = cnt;
    }
}

// ---------------------------------------------------------------------------
// Final deterministic reduce -> loss
// ---------------------------------------------------------------------------
__global__ void k_final(float* out) {
    __shared__ float sc[1024], sn[1024];
    int t = threadIdx.x;
    sc[t] = g_buf[OF_CON + t] + g_buf[OF_CON + 1024 + t];
    sn[t] = g_buf[OF_CNT + t] + g_buf[OF_CNT + 1024 + t];
    __syncthreads();
    for (int o = 512; o > 0; o >>= 1) {
        if (t < o) { sc[t] += sc[t+o]; sn[t] += sn[t+o]; }
        __syncthreads();
    }
    if (t == 0) out[0] = -sc[0] / sn[0];
}

// ---------------------------------------------------------------------------
// Host orchestration (graph-capturable: kernel launches only, default stream)
// ---------------------------------------------------------------------------
extern "C" void kernel_launch(void* const* d_in, const int* in_sizes, int n_in,
                              void* d_out, int out_size)
{
    const int*   src_seqs = (const int*)  d_in[0];
    const int*   src_len  = (const int*)  d_in[1];
    const int*   tgt_seqs = (const int*)  d_in[2];
    const int*   tgt_len  = (const int*)  d_in[3];
    const float* src_emb  = (const float*)d_in[4];
    const float* eWih_f   = (const float*)d_in[5];
    const float* eWhh_f   = (const float*)d_in[6];
    const float* ebih_f   = (const float*)d_in[7];
    const float* ebhh_f   = (const float*)d_in[8];
    const float* eWih_b   = (const float*)d_in[9];
    const float* eWhh_b   = (const float*)d_in[10];
    const float* ebih_b   = (const float*)d_in[11];
    const float* ebhh_b   = (const float*)d_in[12];
    const float* tgt_emb  = (const float*)d_in[13];
    const float* dWih     = (const float*)d_in[14];
    const float* dWhh     = (const float*)d_in[15];
    const float* dbih     = (const float*)d_in[16];
    const float* dbhh     = (const float*)d_in[17];
    const float* U_w      = (const float*)d_in[18];
    const float* U_b      = (const float*)d_in[19];
    const float* A_W      = (const float*)d_in[20];
    const float* A_b      = (const float*)d_in[21];
    const float* A_v      = (const float*)d_in[22];
    const float* out_w    = (const float*)d_in[23];
    const float* out_b    = (const float*)d_in[24];

    k_zero<<<64, 256>>>();
    k_embed<<<2048, 128>>>(src_seqs, src_emb, OF_ESRC);
    k_embed<<<2048, 128>>>(tgt_seqs, tgt_emb, OF_ETGT);

    // input-gate pre-GEMMs (bias folded in), TF32 tensor cores
    k_gemm128<<<dim3(12, 32), 256>>>(OF_ESRC, 512, eWih_f, 512, ebih_f, OF_GXF, 1536, 512, 0);
    k_gemm128<<<dim3(12, 32), 256>>>(OF_ESRC, 512, eWih_b, 512, ebih_b, OF_GXB, 1536, 512, 0);
    k_gemm128<<<dim3(12, 32), 256>>>(OF_ETGT, 512, dWih, 1536, dbih, OF_DGX, 1536, 512, 0);

    for (int s = 0; s < 64; s++)
        k_enc_step<<<128, 128>>>(s, eWhh_f, ebhh_f, eWhh_b, ebhh_b, src_len, s & 1);

    // Uh = src_hidden @ U_w^T + U_b;  P = src_hidden @ Wih_ctx^T (no bias)
    k_gemm128<<<dim3(4, 32), 256>>>(OF_SRCH, 1024, U_w, 1024, U_b, OF_UH, 512, 1024, 0);
    k_gemm128<<<dim3(12, 32), 256>>>(OF_SRCH, 1024, dWih + 512, 1536, (const float*)0, OF_P, 1536, 1024, 0);

    for (int i = 0; i < 64; i++) {
        k_attn<<<32, 256>>>(A_W, A_b, A_v, src_len, i & 1);
        k_dec_step<<<64, 128>>>(i, dWhh, dbhh, tgt_len, i & 1);
    }

    k_gemm128<<<dim3(250, 32), 256>>>(OF_DOUT, 512, out_w, 512, out_b, 0, 0, 512, 1);
    k_combine<<<256, 256>>>(tgt_seqs, out_w, out_b);
    k_final<<<1, 1024>>>((float*)d_out);
}

// round 8
// speedup vs baseline: 1.4147x; 1.2820x over previous
#include <cuda_runtime.h>
#include <mma.h>
#include <math.h>

using namespace nvcuda;

// ---------------------------------------------------------------------------
// Problem constants: B=32, S=T=64, E=H=512, G=3H=1536, V=32000
// ---------------------------------------------------------------------------

#define OF_ESRC 0ul            /* 2048*512  */
#define OF_ETGT 1048576ul      /* 2048*512  */
#define OF_GXF  2097152ul      /* 2048*1536 */
#define OF_GXB  5242880ul      /* 2048*1536 */
#define OF_DGX  8388608ul      /* 2048*1536 */
#define OF_SRCH 11534336ul     /* 2048*1024 */
#define OF_UH   13631488ul     /* 2048*512  */
#define OF_DOUT 14680064ul     /* 2048*512  */
#define OF_HF   15728640ul     /* 2*32*512 double buffer */
#define OF_HB   15761408ul     /* 2*32*512 */
#define OF_HD   15794176ul     /* 2*32*512 */
#define OF_CTX  15826944ul     /* 32*1536 gx_ctx (alpha @ P) */
#define OF_LP   15876096ul     /* 2048*250*2 logits (max,sumexp) partials */
#define OF_CON  16900096ul     /* 2048 */
#define OF_CNT  16902144ul     /* 2048 */
#define OF_P    16904192ul     /* 2048*1536 : P = src_hidden @ Wih_ctx^T */
#define OF_QS   20049920ul     /* 32*512 decoder q = A_W@h + A_b */
#define BUF_TOTAL 20066304ul

__device__ __align__(16) float g_buf[BUF_TOTAL];

// grid-barrier state (reset every replay by k_zero)
__device__ unsigned g_bar_arr[2];
__device__ volatile unsigned g_bar_rel[2];

__device__ __forceinline__ float sigm(float x) { return 1.f / (1.f + __expf(-x)); }
__device__ __forceinline__ float dot4(float4 a, float4 b, float acc) {
    acc = fmaf(a.x, b.x, acc); acc = fmaf(a.y, b.y, acc);
    acc = fmaf(a.z, b.z, acc); acc = fmaf(a.w, b.w, acc);
    return acc;
}
__device__ __forceinline__ float T32(float x) { return wmma::__float_to_tf32(x); }

// Software grid barrier. Requires all blocks co-resident (grid <= 148 SMs).
__device__ __forceinline__ void gridbar(int idx, unsigned e, unsigned nb) {
    __syncthreads();
    if (threadIdx.x == 0) {
        __threadfence();
        unsigned old = atomicAdd(&g_bar_arr[idx], 1u);
        if (old == e * nb + nb - 1u) {
            g_bar_rel[idx] = e + 1u;
        }
        while (g_bar_rel[idx] < e + 1u) {}
        __threadfence();
    }
    __syncthreads();
}

// ---------------------------------------------------------------------------
// zero initial hidden states + barrier state (runs every replay)
// ---------------------------------------------------------------------------
__global__ void k_zero() {
    int i = blockIdx.x * 256 + threadIdx.x;   // grid 64 -> 16384
    g_buf[OF_HF + i] = 0.f;
    g_buf[OF_HB + i] = 0.f;
    g_buf[OF_HD + i] = 0.f;
    if (blockIdx.x == 0 && threadIdx.x < 2) {
        g_bar_arr[threadIdx.x] = 0u;
        g_bar_rel[threadIdx.x] = 0u;
    }
}

// ---------------------------------------------------------------------------
// embedding gather: row r -> table[ids[r]] (512 floats)
// ---------------------------------------------------------------------------
__global__ void k_embed(const int* __restrict__ ids, const float* __restrict__ tab,
                        size_t out_off) {
    int row = blockIdx.x;
    const float4* src = (const float4*)(tab + (size_t)ids[row] * 512);
    float4* dst = (float4*)(g_buf + out_off + (size_t)row * 512);
    dst[threadIdx.x] = src[threadIdx.x];
}

// ---------------------------------------------------------------------------
// TF32 GEMM, BM=128 x BN=128 x BK=16, 256 threads (8 warps 2x4, 64x32/warp).
// Double-buffered smem (stride 20), tf32 rounded at smem-store.
// C[M,N] = A[M,K] @ W[N,K]^T (+bias). A,C in g_buf; W global.
// logits_mode: emit per-row (max, sumexp) partials instead of C.
// dynamic smem = max(2*5120, 128*136) floats = 69632 bytes
// ---------------------------------------------------------------------------
__global__ __launch_bounds__(256) void k_gemm_big(
    size_t a_off, int lda, const float* __restrict__ W, int ldw,
    const float* __restrict__ bias, size_t c_off, int ldc, int K,
    int logits_mode)
{
    extern __shared__ float sm2[];
    __shared__ float bsh[128];
    const float* A = g_buf + a_off;
    int bm = blockIdx.y * 128, bn = blockIdx.x * 128;
    int t = threadIdx.x;
    int wid = t >> 5;
    int wm = (wid >> 2) * 64, wn = (wid & 3) * 32;
    int lr = t >> 1, lc = (t & 1) * 8;

    wmma::fragment<wmma::accumulator, 16, 16, 8, float> acc[4][2];
#pragma unroll
    for (int i = 0; i < 4; i++)
#pragma unroll
        for (int j = 0; j < 2; j++) wmma::fill_fragment(acc[i][j], 0.f);

    // prologue: tile k0=0 -> buf 0
    {
        const float* ap = A + (size_t)(bm + lr) * lda + lc;
        const float* wp = W + (size_t)(bn + lr) * ldw + lc;
        float4 a0 = *(const float4*)ap, a1 = *(const float4*)(ap + 4);
        float4 b0 = *(const float4*)wp, b1 = *(const float4*)(wp + 4);
        float* As = sm2; float* Bs = sm2 + 2560;
        As[lr*20+lc+0]=T32(a0.x); As[lr*20+lc+1]=T32(a0.y);
        As[lr*20+lc+2]=T32(a0.z); As[lr*20+lc+3]=T32(a0.w);
        As[lr*20+lc+4]=T32(a1.x); As[lr*20+lc+5]=T32(a1.y);
        As[lr*20+lc+6]=T32(a1.z); As[lr*20+lc+7]=T32(a1.w);
        Bs[lr*20+lc+0]=T32(b0.x); Bs[lr*20+lc+1]=T32(b0.y);
        Bs[lr*20+lc+2]=T32(b0.z); Bs[lr*20+lc+3]=T32(b0.w);
        Bs[lr*20+lc+4]=T32(b1.x); Bs[lr*20+lc+5]=T32(b1.y);
        Bs[lr*20+lc+6]=T32(b1.z); Bs[lr*20+lc+7]=T32(b1.w);
    }
    __syncthreads();

    int buf = 0;
    for (int k0 = 0; k0 < K; k0 += 16) {
        float4 pa0, pa1, pb0, pb1;
        bool more = (k0 + 16) < K;
        if (more) {
            const float* ap = A + (size_t)(bm + lr) * lda + k0 + 16 + lc;
            const float* wp = W + (size_t)(bn + lr) * ldw + k0 + 16 + lc;
            pa0 = *(const float4*)ap; pa1 = *(const float4*)(ap + 4);
            pb0 = *(const float4*)wp; pb1 = *(const float4*)(wp + 4);
        }
        const float* As = sm2 + buf * 5120;
        const float* Bs = As + 2560;
#pragma unroll
        for (int kk = 0; kk < 16; kk += 8) {
            wmma::fragment<wmma::matrix_a, 16, 16, 8, wmma::precision::tf32,
                           wmma::row_major> af[4];
            wmma::fragment<wmma::matrix_b, 16, 16, 8, wmma::precision::tf32,
                           wmma::col_major> bf[2];
#pragma unroll
            for (int i = 0; i < 4; i++)
                wmma::load_matrix_sync(af[i], As + (wm + i*16) * 20 + kk, 20);
#pragma unroll
            for (int j = 0; j < 2; j++)
                wmma::load_matrix_sync(bf[j], Bs + (wn + j*16) * 20 + kk, 20);
#pragma unroll
            for (int i = 0; i < 4; i++)
#pragma unroll
                for (int j = 0; j < 2; j++)
                    wmma::mma_sync(acc[i][j], af[i], bf[j], acc[i][j]);
        }
        if (more) {
            float* Ad = sm2 + (buf ^ 1) * 5120;
            float* Bd = Ad + 2560;
            Ad[lr*20+lc+0]=T32(pa0.x); Ad[lr*20+lc+1]=T32(pa0.y);
            Ad[lr*20+lc+2]=T32(pa0.z); Ad[lr*20+lc+3]=T32(pa0.w);
            Ad[lr*20+lc+4]=T32(pa1.x); Ad[lr*20+lc+5]=T32(pa1.y);
            Ad[lr*20+lc+6]=T32(pa1.z); Ad[lr*20+lc+7]=T32(pa1.w);
            Bd[lr*20+lc+0]=T32(pb0.x); Bd[lr*20+lc+1]=T32(pb0.y);
            Bd[lr*20+lc+2]=T32(pb0.z); Bd[lr*20+lc+3]=T32(pb0.w);
            Bd[lr*20+lc+4]=T32(pb1.x); Bd[lr*20+lc+5]=T32(pb1.y);
            Bd[lr*20+lc+6]=T32(pb1.z); Bd[lr*20+lc+7]=T32(pb1.w);
        }
        __syncthreads();
        buf ^= 1;
    }

    if (logits_mode && t < 128) bsh[t] = bias[bn + t];
    float* Cs = sm2;   // reuse whole dyn smem: [128][136]
#pragma unroll
    for (int i = 0; i < 4; i++)
#pragma unroll
        for (int j = 0; j < 2; j++)
            wmma::store_matrix_sync(Cs + (wm + i*16) * 136 + wn + j*16,
                                    acc[i][j], 136, wmma::mem_row_major);
    __syncthreads();

    int r = t >> 1, ch = (t & 1) * 64;
    if (!logits_mode) {
        float* C = g_buf + c_off;
#pragma unroll
        for (int c = 0; c < 64; c += 4) {
            float4 v = *(float4*)(Cs + r * 136 + ch + c);
            if (bias) {
                float4 bv = *(const float4*)(bias + bn + ch + c);
                v.x += bv.x; v.y += bv.y; v.z += bv.z; v.w += bv.w;
            }
            *(float4*)(C + (size_t)(bm + r) * ldc + bn + ch + c) = v;
        }
    } else {
        float m = -1e30f;
#pragma unroll 16
        for (int c = 0; c < 64; c++)
            m = fmaxf(m, Cs[r * 136 + ch + c] + bsh[ch + c]);
        m = fmaxf(m, __shfl_xor_sync(0xffffffffu, m, 1));
        float l = 0.f;
#pragma unroll 16
        for (int c = 0; c < 64; c++)
            l += __expf(Cs[r * 136 + ch + c] + bsh[ch + c] - m);
        l += __shfl_xor_sync(0xffffffffu, l, 1);
        if ((t & 1) == 0) {
            size_t row = bm + r;
            g_buf[OF_LP + row * 500 + (size_t)blockIdx.x * 2]     = m;
            g_buf[OF_LP + row * 500 + (size_t)blockIdx.x * 2 + 1] = l;
        }
    }
}

// ---------------------------------------------------------------------------
// Persistent encoder: 128 blocks x 128 thr, 64 steps, grid barrier between.
// Block = (dir, 8 h-cols). Whh slice (24x512) resident in dynamic smem.
// dynamic smem = 24*516*4 = 49536 bytes
// ---------------------------------------------------------------------------
__global__ __launch_bounds__(128) void k_enc_all(
    const float* __restrict__ Whh_f, const float* __restrict__ bhh_f,
    const float* __restrict__ Whh_b, const float* __restrict__ bhh_b,
    const int* __restrict__ slen)
{
    extern __shared__ float wsh[];        // [24][516]
    __shared__ float Hs[32][68];
    int bid = blockIdx.x;
    int dir = bid >> 6;
    int j0 = (bid & 63) * 8;
    const float* Whh = dir ? Whh_b : Whh_f;
    const float* bhh = dir ? bhh_b : bhh_f;
    size_t hb = dir ? OF_HB : OF_HF;
    const float* gx = g_buf + (dir ? OF_GXB : OF_GXF);
    int t = threadIdx.x;

    // load Whh slice once: row wr -> global row (wr>>3)*512 + j0 + (wr&7)
    for (int i = t; i < 24 * 128; i += 128) {
        int wr = i >> 7, c4 = (i & 127) * 4;
        int gw = (wr >> 3) * 512 + j0 + (wr & 7);
        *(float4*)&wsh[wr * 516 + c4] = *(const float4*)(Whh + (size_t)gw * 512 + c4);
    }
    __syncthreads();

    int rp = t >> 3;            // 0..15 -> batch rows rp, rp+16
    int j  = t & 7;
    int jg = j0 + j;
    float br = bhh[jg], bz = bhh[512 + jg], bnn = bhh[1024 + jg];
    int lrow = t >> 2, lkv = (t & 3) * 4;
    int sl0 = slen[rp], sl1 = slen[rp + 16];

    for (int s = 0; s < 64; s++) {
        if (s > 0) gridbar(0, (unsigned)(s - 1), 128);
        int pin = s & 1;
        const float* hin = g_buf + hb + (size_t)pin * 16384;
        float* hout = g_buf + hb + (size_t)(pin ^ 1) * 16384;
        int tt = dir ? (63 - s) : s;
        float ar[2] = {0.f,0.f}, az[2] = {0.f,0.f}, an[2] = {0.f,0.f};

        for (int k0 = 0; k0 < 512; k0 += 64) {
#pragma unroll
            for (int i = 0; i < 4; i++) {
                int kv = lkv + i;
                *(float4*)&Hs[lrow][kv*4] =
                    *(const float4*)(hin + (size_t)lrow*512 + k0 + kv*4);
            }
            __syncthreads();
#pragma unroll
            for (int kv = 0; kv < 16; kv++) {
                float4 h0 = *(const float4*)&Hs[rp][kv*4];
                float4 h1 = *(const float4*)&Hs[rp+16][kv*4];
                float4 wrv = *(const float4*)&wsh[(size_t)j*516 + k0 + kv*4];
                float4 wzv = *(const float4*)&wsh[(size_t)(8+j)*516 + k0 + kv*4];
                float4 wnv = *(const float4*)&wsh[(size_t)(16+j)*516 + k0 + kv*4];
                ar[0] = dot4(h0, wrv, ar[0]); ar[1] = dot4(h1, wrv, ar[1]);
                az[0] = dot4(h0, wzv, az[0]); az[1] = dot4(h1, wzv, az[1]);
                an[0] = dot4(h0, wnv, an[0]); an[1] = dot4(h1, wnv, an[1]);
            }
            __syncthreads();
        }
#pragma unroll
        for (int q = 0; q < 2; q++) {
            int r = rp + q*16;
            size_t grow = (size_t)r*64 + tt;
            float gxr = gx[grow*1536 + jg];
            float gxz = gx[grow*1536 + 512 + jg];
            float gxn = gx[grow*1536 + 1024 + jg];
            float rr = sigm(gxr + ar[q] + br);
            float zz = sigm(gxz + az[q] + bz);
            float nn = tanhf(gxn + rr * (an[q] + bnn));
            float hold = hin[(size_t)r*512 + jg];
            float hnew = (1.f - zz) * nn + zz * hold;
            bool m = tt < (q ? sl1 : sl0);
            hout[(size_t)r*512 + jg] = m ? hnew : hold;
            g_buf[OF_SRCH + grow*1024 + (size_t)dir*512 + jg] = m ? hnew : 0.f;
        }
    }
}

// ---------------------------------------------------------------------------
// Persistent decoder: 96 blocks x 256 thr, 64 steps, 3 grid barriers/step.
//   blocks  0-31 : A-blocks  — scores/softmax + gx_ctx = alpha @ P[b]
//   blocks 32-63 : Q-blocks  — qs[b][16 cols] = A_W-slice @ h  (smem-resident)
//   blocks 32-95 : G-blocks  — GRU: gh = h@Whh^T (smem-resident) + pointwise
// G-gemm overlaps the Q and A phases (it doesn't need ctx until pointwise).
// dynamic smem = (16+24)*516*4 = 82560 bytes
// ---------------------------------------------------------------------------
__global__ __launch_bounds__(256) void k_dec_all(
    const float* __restrict__ A_W, const float* __restrict__ A_b,
    const float* __restrict__ A_v, const float* __restrict__ Whh,
    const float* __restrict__ bhh, const int* __restrict__ slen,
    const int* __restrict__ tlen)
{
    extern __shared__ float dsm[];
    float* awsh = dsm;                // [16][516]
    float* whsh = dsm + 16 * 516;     // [24][516]
    __shared__ float Hs[32][68];
    __shared__ float av[512], qsh[512], es[64];

    int bid = blockIdx.x;
    int t = threadIdx.x;
    bool isA = bid < 32;
    bool isQ = (bid >= 32 && bid < 64);
    bool isG = bid >= 32;
    int b   = bid;          // A-block batch
    int qid = bid - 32;     // Q-block col group (16 q-cols)
    int g   = bid - 32;     // G-block col group (8 h-cols)
    int j0  = g * 8;

    if (isQ) {
        for (int i = t; i < 16 * 128; i += 256) {
            int r = i >> 7, c4 = (i & 127) * 4;
            *(float4*)&awsh[r * 516 + c4] =
                *(const float4*)(A_W + (size_t)(qid*16 + r) * 512 + c4);
        }
    }
    if (isG) {
        for (int i = t; i < 24 * 128; i += 256) {
            int wr = i >> 7, c4 = (i & 127) * 4;
            int gw = (wr >> 3) * 512 + j0 + (wr & 7);
            *(float4*)&whsh[wr * 516 + c4] =
                *(const float4*)(Whh + (size_t)gw * 512 + c4);
        }
    }
    if (isA) { av[t] = A_v[t]; av[t + 256] = A_v[t + 256]; }
    __syncthreads();

    int rp = t >> 3, j = t & 7, jg = j0 + j;
    float br = 0.f, bz = 0.f, bnn = 0.f;
    int tl = 64;
    if (isG) {
        br = bhh[jg]; bz = bhh[512 + jg]; bnn = bhh[1024 + jg];
        tl = tlen[rp];
    }
    int sl = isA ? slen[b] : 0;
    float qb0 = 0.f, qb1 = 0.f;
    if (isQ) { qb0 = A_b[qid*16 + (t & 15)]; qb1 = A_b[qid*16 + ((t + 256) & 15)]; }

    unsigned e = 0;
    for (int step = 0; step < 64; step++) {
        if (step > 0) { gridbar(1, e, 96); e++; }   // h[pin] published
        int pin = step & 1;
        const float* hin = g_buf + OF_HD + (size_t)pin * 16384;
        float* hout = g_buf + OF_HD + (size_t)(pin ^ 1) * 16384;

        // ---- Q phase (blocks 32-63) + G gemm (blocks 32-95), overlapped ----
        if (isQ) {
#pragma unroll
            for (int p = 0; p < 2; p++) {
                int pr = t + p * 256;
                int bb = pr >> 4, jj = pr & 15;
                const float* hrow = hin + (size_t)bb * 512;
                float acc = p ? qb1 : qb0;
                for (int k = 0; k < 512; k += 4)
                    acc = dot4(*(const float4*)&awsh[(size_t)jj*516 + k],
                               *(const float4*)(hrow + k), acc);
                g_buf[OF_QS + (size_t)bb * 512 + qid*16 + jj] = acc;
            }
        }
        float ar = 0.f, az = 0.f, an = 0.f;
        if (isG) {
            for (int k0 = 0; k0 < 512; k0 += 64) {
#pragma unroll
                for (int i = 0; i < 2; i++) {
                    int vec = t * 2 + i;           // 0..511
                    int rr = vec >> 4, kv = vec & 15;
                    *(float4*)&Hs[rr][kv*4] =
                        *(const float4*)(hin + (size_t)rr*512 + k0 + kv*4);
                }
                __syncthreads();
#pragma unroll
                for (int kv = 0; kv < 16; kv++) {
                    float4 h0 = *(const float4*)&Hs[rp][kv*4];
                    float4 wrv = *(const float4*)&whsh[(size_t)j*516 + k0 + kv*4];
                    float4 wzv = *(const float4*)&whsh[(size_t)(8+j)*516 + k0 + kv*4];
                    float4 wnv = *(const float4*)&whsh[(size_t)(16+j)*516 + k0 + kv*4];
                    ar = dot4(h0, wrv, ar);
                    az = dot4(h0, wzv, az);
                    an = dot4(h0, wnv, an);
                }
                __syncthreads();
            }
        }
        gridbar(1, e, 96); e++;                      // qs ready

        // ---- A phase (blocks 0-31) ----
        if (isA) {
            qsh[t]       = g_buf[OF_QS + (size_t)b*512 + t];
            qsh[t + 256] = g_buf[OF_QS + (size_t)b*512 + t + 256];
            __syncthreads();
            int w = t >> 5, lane = t & 31;
#pragma unroll
            for (int si = 0; si < 8; si++) {
                int s = w*8 + si;
                const float* uh = g_buf + OF_UH + ((size_t)b*64 + s)*512;
                float acc = 0.f;
                for (int jq = lane; jq < 512; jq += 32) {
                    float x = uh[jq] + qsh[jq];
                    float th;
                    asm("tanh.approx.f32 %0, %1;" : "=f"(th) : "f"(x));
                    acc = fmaf(av[jq], th, acc);
                }
#pragma unroll
                for (int o = 16; o > 0; o >>= 1)
                    acc += __shfl_xor_sync(0xffffffffu, acc, o);
                if (lane == 0) es[s] = (s < sl) ? acc : acc - 1e9f;
            }
            __syncthreads();
            if (t < 32) {
                float a0 = es[t], a1 = es[t + 32];
                float m = fmaxf(a0, a1);
#pragma unroll
                for (int o = 16; o > 0; o >>= 1)
                    m = fmaxf(m, __shfl_xor_sync(0xffffffffu, m, o));
                float e0 = __expf(a0 - m), e1 = __expf(a1 - m);
                float sum = e0 + e1;
#pragma unroll
                for (int o = 16; o > 0; o >>= 1)
                    sum += __shfl_xor_sync(0xffffffffu, sum, o);
                es[t] = e0 / sum; es[t + 32] = e1 / sum;
            }
            __syncthreads();
            const float* Pb = g_buf + OF_P + (size_t)b * 64 * 1536;
#pragma unroll
            for (int dd = 0; dd < 6; dd++) {
                int d = t + dd * 256;
                float acc = 0.f;
#pragma unroll 8
                for (int s2 = 0; s2 < 64; s2++)
                    acc = fmaf(es[s2], Pb[(size_t)s2*1536 + d], acc);
                g_buf[OF_CTX + (size_t)b*1536 + d] = acc;
            }
        }
        gridbar(1, e, 96); e++;                      // ctx ready

        // ---- pointwise GRU (blocks 32-95) ----
        if (isG) {
            size_t grow = (size_t)rp*64 + step;
            const float* gx = g_buf + OF_DGX + grow*1536;
            const float* gc = g_buf + OF_CTX + (size_t)rp*1536;
            float rr = sigm(gx[jg]        + gc[jg]        + ar + br);
            float zz = sigm(gx[512 + jg]  + gc[512 + jg]  + az + bz);
            float nn = tanhf(gx[1024 + jg] + gc[1024 + jg] + rr * (an + bnn));
            float hold = hin[(size_t)rp*512 + jg];
            float hnew = (1.f - zz) * nn + zz * hold;
            bool m = step < tl;
            hout[(size_t)rp*512 + jg] = m ? hnew : hold;
            g_buf[OF_DOUT + grow*512 + jg] = m ? hnew : 0.f;
        }
    }
}

// ---------------------------------------------------------------------------
// Per-row: combine 250 (m,l) partials -> logZ; picked logit via dot; contrib
// ---------------------------------------------------------------------------
__global__ __launch_bounds__(256) void k_combine(
    const int* __restrict__ tgt, const float* __restrict__ out_w,
    const float* __restrict__ out_b)
{
    int row = blockIdx.x * 8 + (threadIdx.x >> 5);
    int lane = threadIdx.x & 31;
    const float* p = g_buf + OF_LP + (size_t)row * 500;
    float M = -1e30f;
    for (int c = lane; c < 250; c += 32) M = fmaxf(M, p[c*2]);
#pragma unroll
    for (int o = 16; o > 0; o >>= 1) M = fmaxf(M, __shfl_xor_sync(0xffffffffu, M, o));
    float L = 0.f;
    for (int c = lane; c < 250; c += 32) L += p[c*2+1] * __expf(p[c*2] - M);
#pragma unroll
    for (int o = 16; o > 0; o >>= 1) L += __shfl_xor_sync(0xffffffffu, L, o);
    int b = row >> 6, tc = row & 63;
    int goal = (tc < 63) ? tgt[b*64 + tc + 1] : 0;
    float contrib = 0.f, cnt = 0.f;
    if (goal != 0) {
        const float* x = g_buf + OF_DOUT + (size_t)row * 512;
        const float* wrow = out_w + (size_t)goal * 512;
        float d = 0.f;
        for (int k = lane; k < 512; k += 32) d = fmaf(x[k], wrow[k], d);
#pragma unroll
        for (int o = 16; o > 0; o >>= 1) d += __shfl_xor_sync(0xffffffffu, d, o);
        contrib = (d + out_b[goal]) - (M + logf(L));
        cnt = 1.f;
    }
    if (lane == 0) {
        g_buf[OF_CON + row] = contrib;
        g_buf[OF_CNT + row] = cnt;
    }
}

// ---------------------------------------------------------------------------
// Final deterministic reduce -> loss
// ---------------------------------------------------------------------------
__global__ void k_final(float* out) {
    __shared__ float sc[1024], sn[1024];
    int t = threadIdx.x;
    sc[t] = g_buf[OF_CON + t] + g_buf[OF_CON + 1024 + t];
    sn[t] = g_buf[OF_CNT + t] + g_buf[OF_CNT + 1024 + t];
    __syncthreads();
    for (int o = 512; o > 0; o >>= 1) {
        if (t < o) { sc[t] += sc[t+o]; sn[t] += sn[t+o]; }
        __syncthreads();
    }
    if (t == 0) out[0] = -sc[0] / sn[0];
}

// ---------------------------------------------------------------------------
// Host orchestration (graph-capturable: kernel launches only, default stream)
// ---------------------------------------------------------------------------
extern "C" void kernel_launch(void* const* d_in, const int* in_sizes, int n_in,
                              void* d_out, int out_size)
{
    const int*   src_seqs = (const int*)  d_in[0];
    const int*   src_len  = (const int*)  d_in[1];
    const int*   tgt_seqs = (const int*)  d_in[2];
    const int*   tgt_len  = (const int*)  d_in[3];
    const float* src_emb  = (const float*)d_in[4];
    const float* eWih_f   = (const float*)d_in[5];
    const float* eWhh_f   = (const float*)d_in[6];
    const float* ebih_f   = (const float*)d_in[7];
    const float* ebhh_f   = (const float*)d_in[8];
    const float* eWih_b   = (const float*)d_in[9];
    const float* eWhh_b   = (const float*)d_in[10];
    const float* ebih_b   = (const float*)d_in[11];
    const float* ebhh_b   = (const float*)d_in[12];
    const float* tgt_emb  = (const float*)d_in[13];
    const float* dWih     = (const float*)d_in[14];
    const float* dWhh     = (const float*)d_in[15];
    const float* dbih     = (const float*)d_in[16];
    const float* dbhh     = (const float*)d_in[17];
    const float* U_w      = (const float*)d_in[18];
    const float* U_b      = (const float*)d_in[19];
    const float* A_W      = (const float*)d_in[20];
    const float* A_b      = (const float*)d_in[21];
    const float* A_v      = (const float*)d_in[22];
    const float* out_w    = (const float*)d_in[23];
    const float* out_b    = (const float*)d_in[24];

    cudaFuncSetAttribute(k_gemm_big, cudaFuncAttributeMaxDynamicSharedMemorySize, 69632);
    cudaFuncSetAttribute(k_enc_all,  cudaFuncAttributeMaxDynamicSharedMemorySize, 49536);
    cudaFuncSetAttribute(k_dec_all,  cudaFuncAttributeMaxDynamicSharedMemorySize, 82560);

    k_zero<<<64, 256>>>();
    k_embed<<<2048, 128>>>(src_seqs, src_emb, OF_ESRC);
    k_embed<<<2048, 128>>>(tgt_seqs, tgt_emb, OF_ETGT);

    // input-gate pre-GEMMs (bias folded in)
    k_gemm_big<<<dim3(12, 16), 256, 69632>>>(OF_ESRC, 512, eWih_f, 512, ebih_f, OF_GXF, 1536, 512, 0);
    k_gemm_big<<<dim3(12, 16), 256, 69632>>>(OF_ESRC, 512, eWih_b, 512, ebih_b, OF_GXB, 1536, 512, 0);
    k_gemm_big<<<dim3(12, 16), 256, 69632>>>(OF_ETGT, 512, dWih, 1536, dbih, OF_DGX, 1536, 512, 0);

    // persistent bidirectional encoder (single launch, 64 steps)
    k_enc_all<<<128, 128, 49536>>>(eWhh_f, ebhh_f, eWhh_b, ebhh_b, src_len);

    // Uh = src_hidden @ U_w^T + U_b;  P = src_hidden @ Wih_ctx^T
    k_gemm_big<<<dim3(4, 16), 256, 69632>>>(OF_SRCH, 1024, U_w, 1024, U_b, OF_UH, 512, 1024, 0);
    k_gemm_big<<<dim3(12, 16), 256, 69632>>>(OF_SRCH, 1024, dWih + 512, 1536, (const float*)0, OF_P, 1536, 1024, 0);

    // persistent decoder (single launch, 64 steps, attention fused)
    k_dec_all<<<96, 256, 82560>>>(A_W, A_b, A_v, dWhh, dbhh, src_len, tgt_len);

    // logits GEMM with fused log-softmax partials
    k_gemm_big<<<dim3(250, 16), 256, 69632>>>(OF_DOUT, 512, out_w, 512, out_b, 0, 0, 512, 1);
    k_combine<<<256, 256>>>(tgt_seqs, out_w, out_b);
    k_final<<<1, 1024>>>((float*)d_out);
}

// round 9
// speedup vs baseline: 1.6781x; 1.1862x over previous
#include <cuda_runtime.h>
#include <cuda_bf16.h>
#include <mma.h>
#include <math.h>

using namespace nvcuda;

// ---------------------------------------------------------------------------
// Problem constants: B=32, S=T=64, E=H=512, G=3H=1536, V=32000
// ---------------------------------------------------------------------------

#define OF_ESRC 0ul            /* 2048*512  */
#define OF_ETGT 1048576ul      /* 2048*512  */
#define OF_GXF  2097152ul      /* 2048*1536 */
#define OF_GXB  5242880ul      /* 2048*1536 */
#define OF_DGX  8388608ul      /* 2048*1536 */
#define OF_SRCH 11534336ul     /* 2048*1024 */
#define OF_UH   13631488ul     /* 2048*512  */
#define OF_DOUT 14680064ul     /* 2048*512  */
#define OF_HF   15728640ul     /* 2*32*512 double buffer */
#define OF_HB   15761408ul     /* 2*32*512 */
#define OF_HD   15794176ul     /* 2*32*512 */
#define OF_CTX  15826944ul     /* 32*1536 gx_ctx (alpha @ P) */
#define OF_LP   15876096ul     /* 2048*250*2 logits (max,sumexp) partials */
#define OF_CON  16900096ul     /* 2048 */
#define OF_CNT  16902144ul     /* 2048 */
#define OF_P    16904192ul     /* 2048*1536 : P = src_hidden @ Wih_ctx^T */
#define OF_QS   20049920ul     /* 32*512 decoder q = A_W@h + A_b */
#define OF_WB   20066304ul     /* out_w bf16: 16.384M halves = 8.192M floats */
#define OF_DOB  28258304ul     /* dec_out bf16: 1.048M halves = 524288 floats */
#define BUF_TOTAL 28782592ul

__device__ __align__(16) float g_buf[BUF_TOTAL];

// grid-barrier state (reset every replay by k_zero)
__device__ unsigned g_bar_arr[2];
__device__ volatile unsigned g_bar_rel[2];
// logits row compaction + zero-row logZ
__device__ int g_rows[2048];
__device__ int g_nrows;
__device__ float g_M0, g_L0;

__device__ __forceinline__ float sigm(float x) { return 1.f / (1.f + __expf(-x)); }
__device__ __forceinline__ float dot4(float4 a, float4 b, float acc) {
    acc = fmaf(a.x, b.x, acc); acc = fmaf(a.y, b.y, acc);
    acc = fmaf(a.z, b.z, acc); acc = fmaf(a.w, b.w, acc);
    return acc;
}
__device__ __forceinline__ float T32(float x) { return wmma::__float_to_tf32(x); }

// Software grid barrier. Requires all blocks co-resident (grid <= 148 SMs).
__device__ __forceinline__ void gridbar(int idx, unsigned e, unsigned nb) {
    __syncthreads();
    if (threadIdx.x == 0) {
        __threadfence();
        unsigned old = atomicAdd(&g_bar_arr[idx], 1u);
        if (old == e * nb + nb - 1u) {
            g_bar_rel[idx] = e + 1u;
        }
        while (g_bar_rel[idx] < e + 1u) {}
        __threadfence();
    }
    __syncthreads();
}

// ---------------------------------------------------------------------------
// zero initial hidden states + barrier state (runs every replay)
// ---------------------------------------------------------------------------
__global__ void k_zero() {
    int i = blockIdx.x * 256 + threadIdx.x;   // grid 64 -> 16384
    g_buf[OF_HF + i] = 0.f;
    g_buf[OF_HB + i] = 0.f;
    g_buf[OF_HD + i] = 0.f;
    if (blockIdx.x == 0 && threadIdx.x < 2) {
        g_bar_arr[threadIdx.x] = 0u;
        g_bar_rel[threadIdx.x] = 0u;
    }
}

// ---------------------------------------------------------------------------
// Row compaction: list of decoder rows with tc < tlen[b] (dec_out nonzero)
// ---------------------------------------------------------------------------
__global__ void k_compact(const int* __restrict__ tlen) {
    __shared__ int offs[32];
    int t = threadIdx.x;   // 256
    if (t == 0) {
        int a = 0;
        for (int b = 0; b < 32; b++) { offs[b] = a; a += tlen[b]; }
        g_nrows = a;
    }
    __syncthreads();
    for (int i = t; i < 2048; i += 256) g_rows[i] = 2047;
    __syncthreads();
    for (int b = 0; b < 32; b++) {
        int L = tlen[b];
        for (int tc = t; tc < L; tc += 256)
            g_rows[offs[b] + tc] = b * 64 + tc;
    }
}

// ---------------------------------------------------------------------------
// logsumexp of out_b (logZ for all-zero decoder rows)
// ---------------------------------------------------------------------------
__global__ void k_logz0(const float* __restrict__ ob) {
    __shared__ float red[32];
    int t = threadIdx.x;   // 1024
    int lane = t & 31, w = t >> 5;
    float m = -1e30f;
    for (int i = t; i < 32000; i += 1024) m = fmaxf(m, ob[i]);
#pragma unroll
    for (int o = 16; o > 0; o >>= 1) m = fmaxf(m, __shfl_xor_sync(0xffffffffu, m, o));
    if (lane == 0) red[w] = m;
    __syncthreads();
    if (t < 32) {
        float v = red[t];
#pragma unroll
        for (int o = 16; o > 0; o >>= 1) v = fmaxf(v, __shfl_xor_sync(0xffffffffu, v, o));
        if (t == 0) red[0] = v;
    }
    __syncthreads();
    float M = red[0];
    __syncthreads();
    float l = 0.f;
    for (int i = t; i < 32000; i += 1024) l += __expf(ob[i] - M);
#pragma unroll
    for (int o = 16; o > 0; o >>= 1) l += __shfl_xor_sync(0xffffffffu, l, o);
    if (lane == 0) red[w] = l;
    __syncthreads();
    if (t == 0) {
        float s = 0.f;
        for (int i = 0; i < 32; i++) s += red[i];
        g_M0 = M; g_L0 = s;
    }
}

// ---------------------------------------------------------------------------
// fp32 -> bf16 converters (8 elems/thread)
// ---------------------------------------------------------------------------
__device__ __forceinline__ uint4 cvt8(float4 a, float4 b) {
    __nv_bfloat162 h0 = __floats2bfloat162_rn(a.x, a.y);
    __nv_bfloat162 h1 = __floats2bfloat162_rn(a.z, a.w);
    __nv_bfloat162 h2 = __floats2bfloat162_rn(b.x, b.y);
    __nv_bfloat162 h3 = __floats2bfloat162_rn(b.z, b.w);
    uint4 u;
    u.x = *(unsigned*)&h0; u.y = *(unsigned*)&h1;
    u.z = *(unsigned*)&h2; u.w = *(unsigned*)&h3;
    return u;
}
__global__ void k_cvt_ext(const float* __restrict__ src, size_t dst_off, int n8) {
    int i = blockIdx.x * 256 + threadIdx.x;
    if (i >= n8) return;
    float4 a = ((const float4*)src)[i*2];
    float4 b = ((const float4*)src)[i*2 + 1];
    ((uint4*)(g_buf + dst_off))[i] = cvt8(a, b);
}
__global__ void k_cvt_int(size_t src_off, size_t dst_off, int n8) {
    int i = blockIdx.x * 256 + threadIdx.x;
    if (i >= n8) return;
    float4 a = ((const float4*)(g_buf + src_off))[i*2];
    float4 b = ((const float4*)(g_buf + src_off))[i*2 + 1];
    ((uint4*)(g_buf + dst_off))[i] = cvt8(a, b);
}

// ---------------------------------------------------------------------------
// embedding gather: row r -> table[ids[r]] (512 floats)
// ---------------------------------------------------------------------------
__global__ void k_embed(const int* __restrict__ ids, const float* __restrict__ tab,
                        size_t out_off) {
    int row = blockIdx.x;
    const float4* src = (const float4*)(tab + (size_t)ids[row] * 512);
    float4* dst = (float4*)(g_buf + out_off + (size_t)row * 512);
    dst[threadIdx.x] = src[threadIdx.x];
}

// ---------------------------------------------------------------------------
// TF32 GEMM, BM=128 x BN=128 x BK=16, 256 threads (8 warps 2x4, 64x32/warp).
// C[M,N] = A[M,K] @ W[N,K]^T (+bias). A,C in g_buf; W global.
// dynamic smem = 69632 bytes
// ---------------------------------------------------------------------------
__global__ __launch_bounds__(256) void k_gemm_big(
    size_t a_off, int lda, const float* __restrict__ W, int ldw,
    const float* __restrict__ bias, size_t c_off, int ldc, int K)
{
    extern __shared__ float sm2[];
    const float* A = g_buf + a_off;
    int bm = blockIdx.y * 128, bn = blockIdx.x * 128;
    int t = threadIdx.x;
    int wid = t >> 5;
    int wm = (wid >> 2) * 64, wn = (wid & 3) * 32;
    int lr = t >> 1, lc = (t & 1) * 8;

    wmma::fragment<wmma::accumulator, 16, 16, 8, float> acc[4][2];
#pragma unroll
    for (int i = 0; i < 4; i++)
#pragma unroll
        for (int j = 0; j < 2; j++) wmma::fill_fragment(acc[i][j], 0.f);

    {
        const float* ap = A + (size_t)(bm + lr) * lda + lc;
        const float* wp = W + (size_t)(bn + lr) * ldw + lc;
        float4 a0 = *(const float4*)ap, a1 = *(const float4*)(ap + 4);
        float4 b0 = *(const float4*)wp, b1 = *(const float4*)(wp + 4);
        float* As = sm2; float* Bs = sm2 + 2560;
        As[lr*20+lc+0]=T32(a0.x); As[lr*20+lc+1]=T32(a0.y);
        As[lr*20+lc+2]=T32(a0.z); As[lr*20+lc+3]=T32(a0.w);
        As[lr*20+lc+4]=T32(a1.x); As[lr*20+lc+5]=T32(a1.y);
        As[lr*20+lc+6]=T32(a1.z); As[lr*20+lc+7]=T32(a1.w);
        Bs[lr*20+lc+0]=T32(b0.x); Bs[lr*20+lc+1]=T32(b0.y);
        Bs[lr*20+lc+2]=T32(b0.z); Bs[lr*20+lc+3]=T32(b0.w);
        Bs[lr*20+lc+4]=T32(b1.x); Bs[lr*20+lc+5]=T32(b1.y);
        Bs[lr*20+lc+6]=T32(b1.z); Bs[lr*20+lc+7]=T32(b1.w);
    }
    __syncthreads();

    int buf = 0;
    for (int k0 = 0; k0 < K; k0 += 16) {
        float4 pa0, pa1, pb0, pb1;
        bool more = (k0 + 16) < K;
        if (more) {
            const float* ap = A + (size_t)(bm + lr) * lda + k0 + 16 + lc;
            const float* wp = W + (size_t)(bn + lr) * ldw + k0 + 16 + lc;
            pa0 = *(const float4*)ap; pa1 = *(const float4*)(ap + 4);
            pb0 = *(const float4*)wp; pb1 = *(const float4*)(wp + 4);
        }
        const float* As = sm2 + buf * 5120;
        const float* Bs = As + 2560;
#pragma unroll
        for (int kk = 0; kk < 16; kk += 8) {
            wmma::fragment<wmma::matrix_a, 16, 16, 8, wmma::precision::tf32,
                           wmma::row_major> af[4];
            wmma::fragment<wmma::matrix_b, 16, 16, 8, wmma::precision::tf32,
                           wmma::col_major> bf[2];
#pragma unroll
            for (int i = 0; i < 4; i++)
                wmma::load_matrix_sync(af[i], As + (wm + i*16) * 20 + kk, 20);
#pragma unroll
            for (int j = 0; j < 2; j++)
                wmma::load_matrix_sync(bf[j], Bs + (wn + j*16) * 20 + kk, 20);
#pragma unroll
            for (int i = 0; i < 4; i++)
#pragma unroll
                for (int j = 0; j < 2; j++)
                    wmma::mma_sync(acc[i][j], af[i], bf[j], acc[i][j]);
        }
        if (more) {
            float* Ad = sm2 + (buf ^ 1) * 5120;
            float* Bd = Ad + 2560;
            Ad[lr*20+lc+0]=T32(pa0.x); Ad[lr*20+lc+1]=T32(pa0.y);
            Ad[lr*20+lc+2]=T32(pa0.z); Ad[lr*20+lc+3]=T32(pa0.w);
            Ad[lr*20+lc+4]=T32(pa1.x); Ad[lr*20+lc+5]=T32(pa1.y);
            Ad[lr*20+lc+6]=T32(pa1.z); Ad[lr*20+lc+7]=T32(pa1.w);
            Bd[lr*20+lc+0]=T32(pb0.x); Bd[lr*20+lc+1]=T32(pb0.y);
            Bd[lr*20+lc+2]=T32(pb0.z); Bd[lr*20+lc+3]=T32(pb0.w);
            Bd[lr*20+lc+4]=T32(pb1.x); Bd[lr*20+lc+5]=T32(pb1.y);
            Bd[lr*20+lc+6]=T32(pb1.z); Bd[lr*20+lc+7]=T32(pb1.w);
        }
        __syncthreads();
        buf ^= 1;
    }

    float* Cs = sm2;   // [128][136]
#pragma unroll
    for (int i = 0; i < 4; i++)
#pragma unroll
        for (int j = 0; j < 2; j++)
            wmma::store_matrix_sync(Cs + (wm + i*16) * 136 + wn + j*16,
                                    acc[i][j], 136, wmma::mem_row_major);
    __syncthreads();

    int r = t >> 1, ch = (t & 1) * 64;
    float* C = g_buf + c_off;
#pragma unroll
    for (int c = 0; c < 64; c += 4) {
        float4 v = *(float4*)(Cs + r * 136 + ch + c);
        if (bias) {
            float4 bv = *(const float4*)(bias + bn + ch + c);
            v.x += bv.x; v.y += bv.y; v.z += bv.z; v.w += bv.w;
        }
        *(float4*)(C + (size_t)(bm + r) * ldc + bn + ch + c) = v;
    }
}

// ---------------------------------------------------------------------------
// bf16 logits GEMM with fused (max,sumexp) partials and compacted rows.
// BM=128 x BN=128 x BK=32, 256 thr, m16n16k16 bf16 wmma, fp32 accum.
// A rows gathered via g_rows; blocks past g_nrows exit. dyn smem 69632 B.
// ---------------------------------------------------------------------------
__global__ __launch_bounds__(256) void k_logits_bf16(const float* __restrict__ bias)
{
    extern __shared__ float smf[];
    __shared__ float bsh[128];
    __shared__ int rid[128];
    int bm = blockIdx.y * 128;
    if (bm >= g_nrows) return;
    int bn = blockIdx.x * 128;
    int t = threadIdx.x;
    if (t < 128) { rid[t] = g_rows[bm + t]; bsh[t] = bias[bn + t]; }
    __syncthreads();

    const __nv_bfloat16* Ab = (const __nv_bfloat16*)(g_buf + OF_DOB);
    const __nv_bfloat16* Wb = (const __nv_bfloat16*)(g_buf + OF_WB);
    __nv_bfloat16* smh = (__nv_bfloat16*)smf;

    int wid = t >> 5, wm = (wid >> 2) * 64, wn = (wid & 3) * 32;
    int lr = t >> 1, lc = (t & 1) * 16;   // halves
    int arow = rid[lr];

    wmma::fragment<wmma::accumulator, 16, 16, 16, float> acc[4][2];
#pragma unroll
    for (int i = 0; i < 4; i++)
#pragma unroll
        for (int j = 0; j < 2; j++) wmma::fill_fragment(acc[i][j], 0.f);

    {
        const uint4* as = (const uint4*)(Ab + (size_t)arow * 512 + lc);
        const uint4* ws = (const uint4*)(Wb + (size_t)(bn + lr) * 512 + lc);
        uint4 a0 = as[0], a1 = as[1], w0 = ws[0], w1 = ws[1];
        uint4* da = (uint4*)(smh + lr * 40 + lc);
        uint4* db = (uint4*)(smh + 5120 + lr * 40 + lc);
        da[0] = a0; da[1] = a1; db[0] = w0; db[1] = w1;
    }
    __syncthreads();

    int buf = 0;
    for (int k0 = 0; k0 < 512; k0 += 32) {
        uint4 pa0, pa1, pw0, pw1;
        bool more = (k0 + 32) < 512;
        if (more) {
            const uint4* as = (const uint4*)(Ab + (size_t)arow * 512 + k0 + 32 + lc);
            const uint4* ws = (const uint4*)(Wb + (size_t)(bn + lr) * 512 + k0 + 32 + lc);
            pa0 = as[0]; pa1 = as[1]; pw0 = ws[0]; pw1 = ws[1];
        }
        const __nv_bfloat16* As = smh + buf * 10240;
        const __nv_bfloat16* Bs = As + 5120;
#pragma unroll
        for (int kk = 0; kk < 32; kk += 16) {
            wmma::fragment<wmma::matrix_a, 16, 16, 16, __nv_bfloat16,
                           wmma::row_major> af[4];
            wmma::fragment<wmma::matrix_b, 16, 16, 16, __nv_bfloat16,
                           wmma::col_major> bf[2];
#pragma unroll
            for (int i = 0; i < 4; i++)
                wmma::load_matrix_sync(af[i], As + (wm + i*16) * 40 + kk, 40);
#pragma unroll
            for (int j = 0; j < 2; j++)
                wmma::load_matrix_sync(bf[j], Bs + (wn + j*16) * 40 + kk, 40);
#pragma unroll
            for (int i = 0; i < 4; i++)
#pragma unroll
                for (int j = 0; j < 2; j++)
                    wmma::mma_sync(acc[i][j], af[i], bf[j], acc[i][j]);
        }
        if (more) {
            uint4* da = (uint4*)(smh + (buf ^ 1) * 10240 + lr * 40 + lc);
            uint4* db = (uint4*)(smh + (buf ^ 1) * 10240 + 5120 + lr * 40 + lc);
            da[0] = pa0; da[1] = pa1; db[0] = pw0; db[1] = pw1;
        }
        __syncthreads();
        buf ^= 1;
    }

    float* Cs = smf;   // [128][136]
#pragma unroll
    for (int i = 0; i < 4; i++)
#pragma unroll
        for (int j = 0; j < 2; j++)
            wmma::store_matrix_sync(Cs + (wm + i*16) * 136 + wn + j*16,
                                    acc[i][j], 136, wmma::mem_row_major);
    __syncthreads();

    int r = t >> 1, ch = (t & 1) * 64;
    float m = -1e30f;
#pragma unroll 16
    for (int c = 0; c < 64; c++)
        m = fmaxf(m, Cs[r * 136 + ch + c] + bsh[ch + c]);
    m = fmaxf(m, __shfl_xor_sync(0xffffffffu, m, 1));
    float l = 0.f;
#pragma unroll 16
    for (int c = 0; c < 64; c++)
        l += __expf(Cs[r * 136 + ch + c] + bsh[ch + c] - m);
    l += __shfl_xor_sync(0xffffffffu, l, 1);
    if ((t & 1) == 0) {
        size_t orow = (size_t)rid[r];
        g_buf[OF_LP + orow * 500 + (size_t)blockIdx.x * 2]     = m;
        g_buf[OF_LP + orow * 500 + (size_t)blockIdx.x * 2 + 1] = l;
    }
}

// ---------------------------------------------------------------------------
// Persistent encoder: 128 blocks x 256 thr, 64 steps, grid barrier between.
// Block = (dir, 8 h-cols). Whh slice (24x512) resident in dynamic smem.
// dynamic smem = 24*516*4 = 49536 bytes
// ---------------------------------------------------------------------------
__global__ __launch_bounds__(256) void k_enc_all(
    const float* __restrict__ Whh_f, const float* __restrict__ bhh_f,
    const float* __restrict__ Whh_b, const float* __restrict__ bhh_b,
    const int* __restrict__ slen)
{
    extern __shared__ float wsh[];        // [24][516]
    __shared__ float Hs[32][68];
    int bid = blockIdx.x;
    int dir = bid >> 6;
    int j0 = (bid & 63) * 8;
    const float* Whh = dir ? Whh_b : Whh_f;
    const float* bhh = dir ? bhh_b : bhh_f;
    size_t hb = dir ? OF_HB : OF_HF;
    const float* gx = g_buf + (dir ? OF_GXB : OF_GXF);
    int t = threadIdx.x;

    for (int i = t; i < 24 * 128; i += 256) {
        int wr = i >> 7, c4 = (i & 127) * 4;
        int gw = (wr >> 3) * 512 + j0 + (wr & 7);
        *(float4*)&wsh[wr * 516 + c4] = *(const float4*)(Whh + (size_t)gw * 512 + c4);
    }
    __syncthreads();

    int rp = t >> 3;            // 0..31 batch row
    int j  = t & 7;
    int jg = j0 + j;
    float br = bhh[jg], bz = bhh[512 + jg], bnn = bhh[1024 + jg];
    int sl = slen[rp];

    for (int s = 0; s < 64; s++) {
        if (s > 0) gridbar(0, (unsigned)(s - 1), 128);
        int pin = s & 1;
        const float* hin = g_buf + hb + (size_t)pin * 16384;
        float* hout = g_buf + hb + (size_t)(pin ^ 1) * 16384;
        int tt = dir ? (63 - s) : s;
        float ar = 0.f, az = 0.f, an = 0.f;

        for (int k0 = 0; k0 < 512; k0 += 64) {
#pragma unroll
            for (int i = 0; i < 2; i++) {
                int vec = t + 256 * i;       // 0..511
                int rr = vec >> 4, kv = vec & 15;
                *(float4*)&Hs[rr][kv*4] =
                    *(const float4*)(hin + (size_t)rr*512 + k0 + kv*4);
            }
            __syncthreads();
#pragma unroll
            for (int kv = 0; kv < 16; kv++) {
                float4 h0 = *(const float4*)&Hs[rp][kv*4];
                float4 wrv = *(const float4*)&wsh[(size_t)j*516 + k0 + kv*4];
                float4 wzv = *(const float4*)&wsh[(size_t)(8+j)*516 + k0 + kv*4];
                float4 wnv = *(const float4*)&wsh[(size_t)(16+j)*516 + k0 + kv*4];
                ar = dot4(h0, wrv, ar);
                az = dot4(h0, wzv, az);
                an = dot4(h0, wnv, an);
            }
            __syncthreads();
        }
        size_t grow = (size_t)rp*64 + tt;
        float gxr = gx[grow*1536 + jg];
        float gxz = gx[grow*1536 + 512 + jg];
        float gxn = gx[grow*1536 + 1024 + jg];
        float rr = sigm(gxr + ar + br);
        float zz = sigm(gxz + az + bz);
        float nn = tanhf(gxn + rr * (an + bnn));
        float hold = hin[(size_t)rp*512 + jg];
        float hnew = (1.f - zz) * nn + zz * hold;
        bool m = tt < sl;
        hout[(size_t)rp*512 + jg] = m ? hnew : hold;
        g_buf[OF_SRCH + grow*1024 + (size_t)dir*512 + jg] = m ? hnew : 0.f;
    }
}

// ---------------------------------------------------------------------------
// Persistent decoder: 96 blocks x 256 thr, 64 steps, 3 grid barriers/step.
//   blocks  0-31 : A-blocks  — Uh[b] smem-resident; scores/softmax/ctx
//   blocks 32-63 : Q-blocks  — qs = A_W-slice @ h (A_W smem-resident)
//   blocks 32-95 : G-blocks  — gh = h@Whh^T (Whh smem-resident) + pointwise
// dynamic smem = 131072 bytes (A role: Uh 64x512 f32)
// ---------------------------------------------------------------------------
__global__ __launch_bounds__(256) void k_dec_all(
    const float* __restrict__ A_W, const float* __restrict__ A_b,
    const float* __restrict__ A_v, const float* __restrict__ Whh,
    const float* __restrict__ bhh, const int* __restrict__ slen,
    const int* __restrict__ tlen)
{
    extern __shared__ float dsm[];
    float* awsh = dsm;                // Q: [16][516]
    float* whsh = dsm + 16 * 516;     // G: [24][516]
    float* uhs  = dsm;                // A: [64][512]
    __shared__ float Hs[32][68];
    __shared__ float es[64];

    int bid = blockIdx.x;
    int t = threadIdx.x;
    int lane = t & 31;
    bool isA = bid < 32;
    bool isQ = (bid >= 32 && bid < 64);
    bool isG = bid >= 32;
    int b   = bid;          // A-block batch
    int qid = bid - 32;     // Q-block col group (16 q-cols)
    int g   = bid - 32;     // G-block col group (8 h-cols)
    int j0  = g * 8;

    float avr[16], qb0 = 0.f, qb1 = 0.f;
    if (isA) {
        for (int i = t; i < 8192; i += 256)
            *(float4*)&uhs[(size_t)i*4] =
                *(const float4*)(g_buf + OF_UH + (size_t)b*32768 + (size_t)i*4);
#pragma unroll
        for (int k = 0; k < 16; k++) avr[k] = A_v[lane + 32*k];
    }
    if (isQ) {
        for (int i = t; i < 16 * 128; i += 256) {
            int r = i >> 7, c4 = (i & 127) * 4;
            *(float4*)&awsh[r * 516 + c4] =
                *(const float4*)(A_W + (size_t)(qid*16 + r) * 512 + c4);
        }
        qb0 = A_b[qid*16 + (t & 15)];
        qb1 = A_b[qid*16 + ((t + 256) & 15)];
    }
    if (isG) {
        for (int i = t; i < 24 * 128; i += 256) {
            int wr = i >> 7, c4 = (i & 127) * 4;
            int gw = (wr >> 3) * 512 + j0 + (wr & 7);
            *(float4*)&whsh[wr * 516 + c4] =
                *(const float4*)(Whh + (size_t)gw * 512 + c4);
        }
    }
    __syncthreads();

    int rp = t >> 3, j = t & 7, jg = j0 + j;
    float br = 0.f, bz = 0.f, bnn = 0.f;
    int tl = 64;
    if (isG) {
        br = bhh[jg]; bz = bhh[512 + jg]; bnn = bhh[1024 + jg];
        tl = tlen[rp];
    }
    int sl = isA ? slen[b] : 0;

    unsigned e = 0;
    for (int step = 0; step < 64; step++) {
        if (step > 0) { gridbar(1, e, 96); e++; }   // h[pin] published
        int pin = step & 1;
        const float* hin = g_buf + OF_HD + (size_t)pin * 16384;
        float* hout = g_buf + OF_HD + (size_t)(pin ^ 1) * 16384;

        // ---- Q phase + G gemm, overlapped ----
        if (isQ) {
#pragma unroll
            for (int p = 0; p < 2; p++) {
                int pr = t + p * 256;
                int bb = pr >> 4, jj = pr & 15;
                const float* hrow = hin + (size_t)bb * 512;
                float acc = p ? qb1 : qb0;
                for (int k = 0; k < 512; k += 4)
                    acc = dot4(*(const float4*)&awsh[(size_t)jj*516 + k],
                               *(const float4*)(hrow + k), acc);
                g_buf[OF_QS + (size_t)bb * 512 + qid*16 + jj] = acc;
            }
        }
        float ar = 0.f, az = 0.f, an = 0.f;
        if (isG) {
            for (int k0 = 0; k0 < 512; k0 += 64) {
#pragma unroll
                for (int i = 0; i < 2; i++) {
                    int vec = t * 2 + i;           // 0..511
                    int rr = vec >> 4, kv = vec & 15;
                    *(float4*)&Hs[rr][kv*4] =
                        *(const float4*)(hin + (size_t)rr*512 + k0 + kv*4);
                }
                __syncthreads();
#pragma unroll
                for (int kv = 0; kv < 16; kv++) {
                    float4 h0 = *(const float4*)&Hs[rp][kv*4];
                    float4 wrv = *(const float4*)&whsh[(size_t)j*516 + k0 + kv*4];
                    float4 wzv = *(const float4*)&whsh[(size_t)(8+j)*516 + k0 + kv*4];
                    float4 wnv = *(const float4*)&whsh[(size_t)(16+j)*516 + k0 + kv*4];
                    ar = dot4(h0, wrv, ar);
                    az = dot4(h0, wzv, az);
                    an = dot4(h0, wnv, an);
                }
                __syncthreads();
            }
        }
        gridbar(1, e, 96); e++;                      // qs ready

        // ---- A phase ----
        if (isA) {
            float qr[16];
#pragma unroll
            for (int k = 0; k < 16; k++)
                qr[k] = g_buf[OF_QS + (size_t)b*512 + lane + 32*k];
            int w = t >> 5;
#pragma unroll
            for (int si = 0; si < 8; si++) {
                int s = w*8 + si;
                float acc = 0.f;
#pragma unroll
                for (int k = 0; k < 16; k++) {
                    float x = uhs[(size_t)s*512 + lane + 32*k] + qr[k];
                    float th;
                    asm("tanh.approx.f32 %0, %1;" : "=f"(th) : "f"(x));
                    acc = fmaf(avr[k], th, acc);
                }
#pragma unroll
                for (int o = 16; o > 0; o >>= 1)
                    acc += __shfl_xor_sync(0xffffffffu, acc, o);
                if (lane == 0) es[s] = (s < sl) ? acc : acc - 1e9f;
            }
            __syncthreads();
            if (t < 32) {
                float a0 = es[t], a1 = es[t + 32];
                float m = fmaxf(a0, a1);
#pragma unroll
                for (int o = 16; o > 0; o >>= 1)
                    m = fmaxf(m, __shfl_xor_sync(0xffffffffu, m, o));
                float e0 = __expf(a0 - m), e1 = __expf(a1 - m);
                float sum = e0 + e1;
#pragma unroll
                for (int o = 16; o > 0; o >>= 1)
                    sum += __shfl_xor_sync(0xffffffffu, sum, o);
                es[t] = e0 / sum; es[t + 32] = e1 / sum;
            }
            __syncthreads();
            const float* Pb = g_buf + OF_P + (size_t)b * 64 * 1536;
#pragma unroll
            for (int dd = 0; dd < 6; dd++) {
                int d = t + dd * 256;
                float acc = 0.f;
#pragma unroll 8
                for (int s2 = 0; s2 < 64; s2++)
                    acc = fmaf(es[s2], Pb[(size_t)s2*1536 + d], acc);
                g_buf[OF_CTX + (size_t)b*1536 + d] = acc;
            }
        }
        gridbar(1, e, 96); e++;                      // ctx ready

        // ---- pointwise GRU ----
        if (isG) {
            size_t grow = (size_t)rp*64 + step;
            const float* gx = g_buf + OF_DGX + grow*1536;
            const float* gc = g_buf + OF_CTX + (size_t)rp*1536;
            float rr = sigm(gx[jg]        + gc[jg]        + ar + br);
            float zz = sigm(gx[512 + jg]  + gc[512 + jg]  + az + bz);
            float nn = tanhf(gx[1024 + jg] + gc[1024 + jg] + rr * (an + bnn));
            float hold = hin[(size_t)rp*512 + jg];
            float hnew = (1.f - zz) * nn + zz * hold;
            bool m = step < tl;
            hout[(size_t)rp*512 + jg] = m ? hnew : hold;
            g_buf[OF_DOUT + grow*512 + jg] = m ? hnew : 0.f;
        }
    }
}

// ---------------------------------------------------------------------------
// Per-row: combine partials (live rows) or shared logZ0 (zero rows)
// ---------------------------------------------------------------------------
__global__ __launch_bounds__(256) void k_combine(
    const int* __restrict__ tgt, const float* __restrict__ out_w,
    const float* __restrict__ out_b, const int* __restrict__ tlen)
{
    int row = blockIdx.x * 8 + (threadIdx.x >> 5);
    int lane = threadIdx.x & 31;
    int b = row >> 6, tc = row & 63;
    int goal = (tc < 63) ? tgt[b*64 + tc + 1] : 0;
    float contrib = 0.f, cnt = 0.f;
    if (goal != 0) {
        bool live = tc < tlen[b];
        float M, L, d = 0.f;
        if (live) {
            const float* p = g_buf + OF_LP + (size_t)row * 500;
            M = -1e30f;
            for (int c = lane; c < 250; c += 32) M = fmaxf(M, p[c*2]);
#pragma unroll
            for (int o = 16; o > 0; o >>= 1)
                M = fmaxf(M, __shfl_xor_sync(0xffffffffu, M, o));
            L = 0.f;
            for (int c = lane; c < 250; c += 32) L += p[c*2+1] * __expf(p[c*2] - M);
#pragma unroll
            for (int o = 16; o > 0; o >>= 1)
                L += __shfl_xor_sync(0xffffffffu, L, o);
            const float* x = g_buf + OF_DOUT + (size_t)row * 512;
            const float* wrow = out_w + (size_t)goal * 512;
            for (int k = lane; k < 512; k += 32) d = fmaf(x[k], wrow[k], d);
#pragma unroll
            for (int o = 16; o > 0; o >>= 1)
                d += __shfl_xor_sync(0xffffffffu, d, o);
        } else {
            M = g_M0; L = g_L0;
        }
        contrib = (d + out_b[goal]) - (M + logf(L));
        cnt = 1.f;
    }
    if (lane == 0) {
        g_buf[OF_CON + row] = contrib;
        g_buf[OF_CNT + row] = cnt;
    }
}

// ---------------------------------------------------------------------------
// Final deterministic reduce -> loss
// ---------------------------------------------------------------------------
__global__ void k_final(float* out) {
    __shared__ float sc[1024], sn[1024];
    int t = threadIdx.x;
    sc[t] = g_buf[OF_CON + t] + g_buf[OF_CON + 1024 + t];
    sn[t] = g_buf[OF_CNT + t] + g_buf[OF_CNT + 1024 + t];
    __syncthreads();
    for (int o = 512; o > 0; o >>= 1) {
        if (t < o) { sc[t] += sc[t+o]; sn[t] += sn[t+o]; }
        __syncthreads();
    }
    if (t == 0) out[0] = -sc[0] / sn[0];
}

// ---------------------------------------------------------------------------
// Host orchestration (graph-capturable: kernel launches only, default stream)
// ---------------------------------------------------------------------------
extern "C" void kernel_launch(void* const* d_in, const int* in_sizes, int n_in,
                              void* d_out, int out_size)
{
    const int*   src_seqs = (const int*)  d_in[0];
    const int*   src_len  = (const int*)  d_in[1];
    const int*   tgt_seqs = (const int*)  d_in[2];
    const int*   tgt_len  = (const int*)  d_in[3];
    const float* src_emb  = (const float*)d_in[4];
    const float* eWih_f   = (const float*)d_in[5];
    const float* eWhh_f   = (const float*)d_in[6];
    const float* ebih_f   = (const float*)d_in[7];
    const float* ebhh_f   = (const float*)d_in[8];
    const float* eWih_b   = (const float*)d_in[9];
    const float* eWhh_b   = (const float*)d_in[10];
    const float* ebih_b   = (const float*)d_in[11];
    const float* ebhh_b   = (const float*)d_in[12];
    const float* tgt_emb  = (const float*)d_in[13];
    const float* dWih     = (const float*)d_in[14];
    const float* dWhh     = (const float*)d_in[15];
    const float* dbih     = (const float*)d_in[16];
    const float* dbhh     = (const float*)d_in[17];
    const float* U_w      = (const float*)d_in[18];
    const float* U_b      = (const float*)d_in[19];
    const float* A_W      = (const float*)d_in[20];
    const float* A_b      = (const float*)d_in[21];
    const float* A_v      = (const float*)d_in[22];
    const float* out_w    = (const float*)d_in[23];
    const float* out_b    = (const float*)d_in[24];

    cudaFuncSetAttribute(k_gemm_big,    cudaFuncAttributeMaxDynamicSharedMemorySize, 69632);
    cudaFuncSetAttribute(k_logits_bf16, cudaFuncAttributeMaxDynamicSharedMemorySize, 69632);
    cudaFuncSetAttribute(k_enc_all,     cudaFuncAttributeMaxDynamicSharedMemorySize, 49536);
    cudaFuncSetAttribute(k_dec_all,     cudaFuncAttributeMaxDynamicSharedMemorySize, 131072);

    k_zero<<<64, 256>>>();
    k_compact<<<1, 256>>>(tgt_len);
    k_logz0<<<1, 1024>>>(out_b);
    k_cvt_ext<<<8000, 256>>>(out_w, OF_WB, 2048000);
    k_embed<<<2048, 128>>>(src_seqs, src_emb, OF_ESRC);
    k_embed<<<2048, 128>>>(tgt_seqs, tgt_emb, OF_ETGT);

    // input-gate pre-GEMMs (bias folded in)
    k_gemm_big<<<dim3(12, 16), 256, 69632>>>(OF_ESRC, 512, eWih_f, 512, ebih_f, OF_GXF, 1536, 512);
    k_gemm_big<<<dim3(12, 16), 256, 69632>>>(OF_ESRC, 512, eWih_b, 512, ebih_b, OF_GXB, 1536, 512);
    k_gemm_big<<<dim3(12, 16), 256, 69632>>>(OF_ETGT, 512, dWih, 1536, dbih, OF_DGX, 1536, 512);

    // persistent bidirectional encoder (single launch, 64 steps)
    k_enc_all<<<128, 256, 49536>>>(eWhh_f, ebhh_f, eWhh_b, ebhh_b, src_len);

    // Uh = src_hidden @ U_w^T + U_b;  P = src_hidden @ Wih_ctx^T
    k_gemm_big<<<dim3(4, 16), 256, 69632>>>(OF_SRCH, 1024, U_w, 1024, U_b, OF_UH, 512, 1024);
    k_gemm_big<<<dim3(12, 16), 256, 69632>>>(OF_SRCH, 1024, dWih + 512, 1536, (const float*)0, OF_P, 1536, 1024);

    // persistent decoder (single launch, 64 steps, attention fused)
    k_dec_all<<<96, 256, 131072>>>(A_W, A_b, A_v, dWhh, dbhh, src_len, tgt_len);

    // logits: bf16 convert + compacted-row GEMM with fused log-softmax partials
    k_cvt_int<<<512, 256>>>(OF_DOUT, OF_DOB, 131072);
    k_logits_bf16<<<dim3(250, 16), 256, 69632>>>(out_b);
    k_combine<<<256, 256>>>(tgt_seqs, out_w, out_b, tgt_len);
    k_final<<<1, 1024>>>((float*)d_out);
}

// round 10
// speedup vs baseline: 2.6053x; 1.5526x over previous
#include <cuda_runtime.h>
#include <cuda_bf16.h>
#include <mma.h>
#include <math.h>

using namespace nvcuda;

// ---------------------------------------------------------------------------
// Problem constants: B=32, S=T=64, E=H=512, G=3H=1536, V=32000
// ---------------------------------------------------------------------------

#define OF_ESRCB 0ul          /* bf16 2048x512  (524288 f) */
#define OF_ETGTB 524288ul     /* bf16 2048x512  */
#define OF_GXF   1048576ul    /* f32 2048x1536  */
#define OF_GXB   4194304ul
#define OF_DGX   7340032ul
#define OF_SRCHB 10485760ul   /* bf16 2048x1024 (1048576 f) */
#define OF_UH    11534336ul   /* f32 2048x512   */
#define OF_DOUT  12582912ul   /* f32 2048x512   */
#define OF_DOB   13631488ul   /* bf16 2048x512  */
#define OF_HF    14155776ul   /* 2*32*512 double buffer */
#define OF_HB    14188544ul
#define OF_HD    14221312ul
#define OF_QS    14254080ul   /* 32*512 */
#define OF_AL    14270464ul   /* 32*64  */
#define OF_LP    14272512ul   /* 2048*250*2 */
#define OF_CON   15296512ul
#define OF_CNT   15298560ul
#define OF_PB    15300608ul   /* bf16 PT: [32][1536][64] (1572864 f) */
#define OF_WF16  16873472ul   /* bf16 1536x512  */
#define OF_WB16  17266688ul
#define OF_WD16  17659904ul   /* bf16 1536x1536 */
#define OF_UW16  18839552ul   /* bf16 512x1024  */
#define OF_OW16  19101696ul   /* bf16 32000x512 */
#define BUF_TOTAL 27293696ul

__device__ __align__(16) float g_buf[BUF_TOTAL];

// grid-barrier state (reset every replay by k_zero)
__device__ unsigned g_bar_arr[4];
__device__ volatile unsigned g_bar_rel[4];
// logits row compaction + zero-row logZ
__device__ int g_rows[2048];
__device__ int g_nrows;
__device__ float g_M0, g_L0;

__device__ __forceinline__ float sigm(float x) { return 1.f / (1.f + __expf(-x)); }
__device__ __forceinline__ float dot4(float4 a, float4 b, float acc) {
    acc = fmaf(a.x, b.x, acc); acc = fmaf(a.y, b.y, acc);
    acc = fmaf(a.z, b.z, acc); acc = fmaf(a.w, b.w, acc);
    return acc;
}

// Software grid barrier. Requires all participating blocks co-resident.
__device__ __forceinline__ void gridbar(int idx, unsigned e, unsigned nb) {
    __syncthreads();
    if (threadIdx.x == 0) {
        __threadfence();
        unsigned old = atomicAdd(&g_bar_arr[idx], 1u);
        if (old == e * nb + nb - 1u) {
            g_bar_rel[idx] = e + 1u;
        }
        while (g_bar_rel[idx] < e + 1u) {}
        __threadfence();
    }
    __syncthreads();
}

// ---------------------------------------------------------------------------
// zero initial hidden states + barrier state (runs every replay)
// ---------------------------------------------------------------------------
__global__ void k_zero() {
    int i = blockIdx.x * 256 + threadIdx.x;   // grid 64 -> 16384 (pin-0 bufs)
    g_buf[OF_HF + i] = 0.f;
    g_buf[OF_HB + i] = 0.f;
    g_buf[OF_HD + i] = 0.f;
    if (blockIdx.x == 0 && threadIdx.x < 4) {
        g_bar_arr[threadIdx.x] = 0u;
        g_bar_rel[threadIdx.x] = 0u;
    }
}

// ---------------------------------------------------------------------------
// Row compaction: list of decoder rows with tc < tlen[b] (dec_out nonzero)
// ---------------------------------------------------------------------------
__global__ void k_compact(const int* __restrict__ tlen) {
    __shared__ int offs[32];
    int t = threadIdx.x;   // 256
    if (t == 0) {
        int a = 0;
        for (int b = 0; b < 32; b++) { offs[b] = a; a += tlen[b]; }
        g_nrows = a;
    }
    __syncthreads();
    for (int i = t; i < 2048; i += 256) g_rows[i] = 2047;
    __syncthreads();
    for (int b = 0; b < 32; b++) {
        int L = tlen[b];
        for (int tc = t; tc < L; tc += 256)
            g_rows[offs[b] + tc] = b * 64 + tc;
    }
}

// ---------------------------------------------------------------------------
// logsumexp of out_b (logZ for all-zero decoder rows)
// ---------------------------------------------------------------------------
__global__ void k_logz0(const float* __restrict__ ob) {
    __shared__ float red[32];
    int t = threadIdx.x;   // 1024
    int lane = t & 31, w = t >> 5;
    float m = -1e30f;
    for (int i = t; i < 32000; i += 1024) m = fmaxf(m, ob[i]);
#pragma unroll
    for (int o = 16; o > 0; o >>= 1) m = fmaxf(m, __shfl_xor_sync(0xffffffffu, m, o));
    if (lane == 0) red[w] = m;
    __syncthreads();
    if (t < 32) {
        float v = red[t];
#pragma unroll
        for (int o = 16; o > 0; o >>= 1) v = fmaxf(v, __shfl_xor_sync(0xffffffffu, v, o));
        if (t == 0) red[0] = v;
    }
    __syncthreads();
    float M = red[0];
    __syncthreads();
    float l = 0.f;
    for (int i = t; i < 32000; i += 1024) l += __expf(ob[i] - M);
#pragma unroll
    for (int o = 16; o > 0; o >>= 1) l += __shfl_xor_sync(0xffffffffu, l, o);
    if (lane == 0) red[w] = l;
    __syncthreads();
    if (t == 0) {
        float s = 0.f;
        for (int i = 0; i < 32; i++) s += red[i];
        g_M0 = M; g_L0 = s;
    }
}

// ---------------------------------------------------------------------------
// fp32 -> bf16 converters (8 elems/thread)
// ---------------------------------------------------------------------------
__device__ __forceinline__ uint4 cvt8(float4 a, float4 b) {
    __nv_bfloat162 h0 = __floats2bfloat162_rn(a.x, a.y);
    __nv_bfloat162 h1 = __floats2bfloat162_rn(a.z, a.w);
    __nv_bfloat162 h2 = __floats2bfloat162_rn(b.x, b.y);
    __nv_bfloat162 h3 = __floats2bfloat162_rn(b.z, b.w);
    uint4 u;
    u.x = *(unsigned*)&h0; u.y = *(unsigned*)&h1;
    u.z = *(unsigned*)&h2; u.w = *(unsigned*)&h3;
    return u;
}
__global__ void k_cvt_ext(const float* __restrict__ src, size_t dst_off, int n8) {
    int i = blockIdx.x * 256 + threadIdx.x;
    if (i >= n8) return;
    float4 a = ((const float4*)src)[i*2];
    float4 b = ((const float4*)src)[i*2 + 1];
    ((uint4*)(g_buf + dst_off))[i] = cvt8(a, b);
}
__global__ void k_cvt_int(size_t src_off, size_t dst_off, int n8) {
    int i = blockIdx.x * 256 + threadIdx.x;
    if (i >= n8) return;
    float4 a = ((const float4*)(g_buf + src_off))[i*2];
    float4 b = ((const float4*)(g_buf + src_off))[i*2 + 1];
    ((uint4*)(g_buf + dst_off))[i] = cvt8(a, b);
}

// ---------------------------------------------------------------------------
// embedding gather -> bf16: row r -> table[ids[r]] (512 vals)
// ---------------------------------------------------------------------------
__global__ void k_embed16(const int* __restrict__ ids, const float* __restrict__ tab,
                          size_t dst_off) {
    int row = blockIdx.x;
    int t = threadIdx.x;   // 128
    float4 v = ((const float4*)(tab + (size_t)ids[row] * 512))[t];
    __nv_bfloat162 h0 = __floats2bfloat162_rn(v.x, v.y);
    __nv_bfloat162 h1 = __floats2bfloat162_rn(v.z, v.w);
    uint2 u; u.x = *(unsigned*)&h0; u.y = *(unsigned*)&h1;
    ((uint2*)(g_buf + dst_off))[(size_t)row * 128 + t] = u;
}

// ---------------------------------------------------------------------------
// bf16 GEMM mainloop macro: BM=128 BN=128 BK=32, 256 thr (8 warps 2x4),
// double-buffered smem (stride 40 halves). Needs: bn, lr, lc, wm, wn, smh, acc.
// ---------------------------------------------------------------------------
#define BF16_MAINLOOP(ApRow, Wp, ldw_, K_)                                          \
    {                                                                               \
        const uint4* as_ = (const uint4*)(ApRow);                                   \
        const uint4* ws_ = (const uint4*)((Wp) + (size_t)(bn + lr) * (ldw_) + lc);  \
        uint4 a0_ = as_[0], a1_ = as_[1], w0_ = ws_[0], w1_ = ws_[1];               \
        uint4* da_ = (uint4*)(smh + lr * 40 + lc);                                  \
        uint4* db_ = (uint4*)(smh + 5120 + lr * 40 + lc);                           \
        da_[0] = a0_; da_[1] = a1_; db_[0] = w0_; db_[1] = w1_;                     \
    }                                                                               \
    __syncthreads();                                                                \
    {                                                                               \
        int buf_ = 0;                                                               \
        for (int k0_ = 0; k0_ < (K_); k0_ += 32) {                                  \
            uint4 pa0_, pa1_, pw0_, pw1_;                                           \
            bool more_ = (k0_ + 32) < (K_);                                         \
            if (more_) {                                                            \
                const uint4* as_ = (const uint4*)((ApRow) + k0_ + 32);              \
                const uint4* ws_ = (const uint4*)((Wp) + (size_t)(bn + lr) * (ldw_) + k0_ + 32 + lc); \
                pa0_ = as_[0]; pa1_ = as_[1]; pw0_ = ws_[0]; pw1_ = ws_[1];         \
            }                                                                       \
            const __nv_bfloat16* As_ = smh + buf_ * 10240;                          \
            const __nv_bfloat16* Bs_ = As_ + 5120;                                  \
            _Pragma("unroll")                                                       \
            for (int kk_ = 0; kk_ < 32; kk_ += 16) {                                \
                wmma::fragment<wmma::matrix_a, 16, 16, 16, __nv_bfloat16,           \
                               wmma::row_major> af_[4];                             \
                wmma::fragment<wmma::matrix_b, 16, 16, 16, __nv_bfloat16,           \
                               wmma::col_major> bf_[2];                             \
                _Pragma("unroll")                                                   \
                for (int i_ = 0; i_ < 4; i_++)                                      \
                    wmma::load_matrix_sync(af_[i_], As_ + (wm + i_*16)*40 + kk_, 40); \
                _Pragma("unroll")                                                   \
                for (int j_ = 0; j_ < 2; j_++)                                      \
                    wmma::load_matrix_sync(bf_[j_], Bs_ + (wn + j_*16)*40 + kk_, 40); \
                _Pragma("unroll")                                                   \
                for (int i_ = 0; i_ < 4; i_++)                                      \
                    _Pragma("unroll")                                               \
                    for (int j_ = 0; j_ < 2; j_++)                                  \
                        wmma::mma_sync(acc[i_][j_], af_[i_], bf_[j_], acc[i_][j_]); \
            }                                                                       \
            if (more_) {                                                            \
                uint4* da_ = (uint4*)(smh + (buf_^1)*10240 + lr*40 + lc);           \
                uint4* db_ = (uint4*)(smh + (buf_^1)*10240 + 5120 + lr*40 + lc);    \
                da_[0] = pa0_; da_[1] = pa1_; db_[0] = pw0_; db_[1] = pw1_;         \
            }                                                                       \
            __syncthreads();                                                        \
            buf_ ^= 1;                                                              \
        }                                                                           \
    }

// Generic two-pass epilogue: Cs fp32 [128][72], write bias-added fp32 rowmajor
// or bf16 P-transposed [b][col][s].
#define BF16_EPILOGUE_STORE(bias_, c_off_, ldc_, omode_)                            \
    {                                                                               \
        float* Cs = (float*)smh;                                                    \
        int slot = (wid & 3) * 16;                                                  \
        int r_ = t >> 1, hb2_ = (t & 1) * 2;                                        \
        _Pragma("unroll")                                                           \
        for (int p_ = 0; p_ < 2; p_++) {                                            \
            __syncthreads();                                                        \
            _Pragma("unroll")                                                       \
            for (int i_ = 0; i_ < 4; i_++)                                          \
                wmma::store_matrix_sync(Cs + (size_t)(wm + i_*16)*72 + slot,        \
                                        acc[i_][p_], 72, wmma::mem_row_major);      \
            __syncthreads();                                                        \
            for (int cp_ = 0; cp_ < 2; cp_++) {                                     \
                int chunk_ = hb2_ + cp_;                                            \
                int gc0_ = bn + chunk_*32 + p_*16;                                  \
                if ((omode_) == 0) {                                                \
                    float* Crow = g_buf + (c_off_) + (size_t)(bm + r_)*(ldc_) + gc0_; \
                    for (int v_ = 0; v_ < 16; v_ += 4) {                            \
                        float4 x = *(float4*)(Cs + (size_t)r_*72 + chunk_*16 + v_); \
                        if (bias_) {                                                \
                            float4 bv = *(const float4*)((bias_) + gc0_ + v_);      \
                            x.x += bv.x; x.y += bv.y; x.z += bv.z; x.w += bv.w;     \
                        }                                                           \
                        *(float4*)(Crow + v_) = x;                                  \
                    }                                                               \
                } else {                                                            \
                    int b_ = (bm + r_) >> 6, s_ = (bm + r_) & 63;                   \
                    __nv_bfloat16* Pt = ((__nv_bfloat16*)g_buf) + 2*OF_PB;          \
                    for (int v_ = 0; v_ < 16; v_++) {                               \
                        float x = Cs[(size_t)r_*72 + chunk_*16 + v_];               \
                        Pt[(size_t)b_*98304 + (size_t)(gc0_ + v_)*64 + s_] =        \
                            __float2bfloat16(x);                                    \
                    }                                                               \
                }                                                                   \
            }                                                                       \
        }                                                                           \
    }

// ---------------------------------------------------------------------------
// Generic bf16 GEMM: C = A @ W^T (+bias). dyn smem 40960 B.
// ---------------------------------------------------------------------------
__global__ __launch_bounds__(256) void k_gemm16(
    size_t a_hoff, int lda, size_t w_hoff, int ldw,
    const float* __restrict__ bias, size_t c_off, int ldc, int K, int omode)
{
    extern __shared__ __nv_bfloat16 smh[];
    const __nv_bfloat16* A = ((const __nv_bfloat16*)g_buf) + a_hoff;
    const __nv_bfloat16* W = ((const __nv_bfloat16*)g_buf) + w_hoff;
    int bm = blockIdx.y * 128, bn = blockIdx.x * 128;
    int t = threadIdx.x, wid = t >> 5;
    int wm = (wid >> 2) * 64, wn = (wid & 3) * 32;
    int lr = t >> 1, lc = (t & 1) * 16;
    const __nv_bfloat16* Arow = A + (size_t)(bm + lr) * lda + lc;
    wmma::fragment<wmma::accumulator, 16, 16, 16, float> acc[4][2];
#pragma unroll
    for (int i = 0; i < 4; i++)
#pragma unroll
        for (int j = 0; j < 2; j++) wmma::fill_fragment(acc[i][j], 0.f);
    BF16_MAINLOOP(Arow, W, ldw, K)
    BF16_EPILOGUE_STORE(bias, c_off, ldc, omode)
}

// ---------------------------------------------------------------------------
// Fused gate pre-GEMMs: seg 0=GXF(ESRC,Wf) 1=GXB(ESRC,Wb) 2=DGX(ETGT,dWih emb)
// grid (36, 16)
// ---------------------------------------------------------------------------
__global__ __launch_bounds__(256) void k_gates16(
    const float* __restrict__ bf, const float* __restrict__ bb,
    const float* __restrict__ bd)
{
    extern __shared__ __nv_bfloat16 smh[];
    int seg = blockIdx.x / 12, xb = blockIdx.x % 12;
    size_t a_hoff = (seg == 2) ? 2*OF_ETGTB : 2*OF_ESRCB;
    size_t w_hoff = (seg == 0) ? 2*OF_WF16 : (seg == 1) ? 2*OF_WB16 : 2*OF_WD16;
    int ldw = (seg == 2) ? 1536 : 512;
    const float* bias = (seg == 0) ? bf : (seg == 1) ? bb : bd;
    size_t c_off = (seg == 0) ? OF_GXF : (seg == 1) ? OF_GXB : OF_DGX;

    const __nv_bfloat16* A = ((const __nv_bfloat16*)g_buf) + a_hoff;
    const __nv_bfloat16* W = ((const __nv_bfloat16*)g_buf) + w_hoff;
    int bm = blockIdx.y * 128, bn = xb * 128;
    int t = threadIdx.x, wid = t >> 5;
    int wm = (wid >> 2) * 64, wn = (wid & 3) * 32;
    int lr = t >> 1, lc = (t & 1) * 16;
    const __nv_bfloat16* Arow = A + (size_t)(bm + lr) * 512 + lc;
    wmma::fragment<wmma::accumulator, 16, 16, 16, float> acc[4][2];
#pragma unroll
    for (int i = 0; i < 4; i++)
#pragma unroll
        for (int j = 0; j < 2; j++) wmma::fill_fragment(acc[i][j], 0.f);
    BF16_MAINLOOP(Arow, W, ldw, 512)
    BF16_EPILOGUE_STORE(bias, c_off, 1536, 0)
}

// ---------------------------------------------------------------------------
// bf16 logits GEMM with fused (max,sumexp) partials + compacted rows.
// grid (250, 16); dyn smem 40960 B (2 blocks/SM).
// ---------------------------------------------------------------------------
__global__ __launch_bounds__(256) void k_logits16(const float* __restrict__ bias)
{
    extern __shared__ __nv_bfloat16 smh[];
    __shared__ float bsh[128];
    __shared__ int rid[128];
    int bm = blockIdx.y * 128;
    if (bm >= g_nrows) return;
    int bn = blockIdx.x * 128;
    int t = threadIdx.x, wid = t >> 5;
    if (t < 128) { rid[t] = g_rows[bm + t]; bsh[t] = bias[bn + t]; }
    __syncthreads();
    int wm = (wid >> 2) * 64, wn = (wid & 3) * 32;
    int lr = t >> 1, lc = (t & 1) * 16;
    const __nv_bfloat16* A = ((const __nv_bfloat16*)g_buf) + 2*OF_DOB;
    const __nv_bfloat16* W = ((const __nv_bfloat16*)g_buf) + 2*OF_OW16;
    const __nv_bfloat16* Arow = A + (size_t)rid[lr] * 512 + lc;
    wmma::fragment<wmma::accumulator, 16, 16, 16, float> acc[4][2];
#pragma unroll
    for (int i = 0; i < 4; i++)
#pragma unroll
        for (int j = 0; j < 2; j++) wmma::fill_fragment(acc[i][j], 0.f);
    BF16_MAINLOOP(Arow, W, 512, 512)

    float* Cs = (float*)smh;
    int slot = (wid & 3) * 16;
    int r = t >> 1, hb2 = (t & 1) * 2;
    float M = -1e30f, Ls = 0.f;
#pragma unroll
    for (int p = 0; p < 2; p++) {
        __syncthreads();
#pragma unroll
        for (int i = 0; i < 4; i++)
            wmma::store_matrix_sync(Cs + (size_t)(wm + i*16)*72 + slot,
                                    acc[i][p], 72, wmma::mem_row_major);
        __syncthreads();
        float m = -1e30f;
        float vals[32];
        for (int cp = 0; cp < 2; cp++) {
            int chunk = hb2 + cp;
#pragma unroll
            for (int v = 0; v < 16; v++) {
                float x = Cs[(size_t)r*72 + chunk*16 + v] + bsh[chunk*32 + p*16 + v];
                vals[cp*16 + v] = x; m = fmaxf(m, x);
            }
        }
        m = fmaxf(m, __shfl_xor_sync(0xffffffffu, m, 1));
        float l = 0.f;
#pragma unroll
        for (int c = 0; c < 32; c++) l += __expf(vals[c] - m);
        l += __shfl_xor_sync(0xffffffffu, l, 1);
        float nM = fmaxf(M, m);
        Ls = Ls * __expf(M - nM) + l * __expf(m - nM);
        M = nM;
    }
    if ((t & 1) == 0) {
        size_t orow = (size_t)rid[r];
        g_buf[OF_LP + orow*500 + (size_t)blockIdx.x*2]     = M;
        g_buf[OF_LP + orow*500 + (size_t)blockIdx.x*2 + 1] = Ls;
    }
}

// ---------------------------------------------------------------------------
// Persistent encoder: 128 blocks x 256 thr, 64 steps, grid barrier (idx 0).
// Whh slice smem-resident; writes src_hidden as bf16. dyn smem 49536 B.
// ---------------------------------------------------------------------------
__global__ __launch_bounds__(256) void k_enc_all(
    const float* __restrict__ Whh_f, const float* __restrict__ bhh_f,
    const float* __restrict__ Whh_b, const float* __restrict__ bhh_b,
    const int* __restrict__ slen)
{
    extern __shared__ float wsh[];        // [24][516]
    __shared__ float Hs[32][68];
    int bid = blockIdx.x;
    int dir = bid >> 6;
    int j0 = (bid & 63) * 8;
    const float* Whh = dir ? Whh_b : Whh_f;
    const float* bhh = dir ? bhh_b : bhh_f;
    size_t hb = dir ? OF_HB : OF_HF;
    const float* gx = g_buf + (dir ? OF_GXB : OF_GXF);
    __nv_bfloat16* srch = ((__nv_bfloat16*)g_buf) + 2*OF_SRCHB;
    int t = threadIdx.x;

    for (int i = t; i < 24 * 128; i += 256) {
        int wr = i >> 7, c4 = (i & 127) * 4;
        int gw = (wr >> 3) * 512 + j0 + (wr & 7);
        *(float4*)&wsh[wr * 516 + c4] = *(const float4*)(Whh + (size_t)gw * 512 + c4);
    }
    __syncthreads();

    int rp = t >> 3;
    int j  = t & 7;
    int jg = j0 + j;
    float br = bhh[jg], bz = bhh[512 + jg], bnn = bhh[1024 + jg];
    int sl = slen[rp];

    for (int s = 0; s < 64; s++) {
        if (s > 0) gridbar(0, (unsigned)(s - 1), 128);
        int pin = s & 1;
        const float* hin = g_buf + hb + (size_t)pin * 16384;
        float* hout = g_buf + hb + (size_t)(pin ^ 1) * 16384;
        int tt = dir ? (63 - s) : s;
        float ar = 0.f, az = 0.f, an = 0.f;

        for (int k0 = 0; k0 < 512; k0 += 64) {
#pragma unroll
            for (int i = 0; i < 2; i++) {
                int vec = t + 256 * i;       // 0..511
                int rr = vec >> 4, kv = vec & 15;
                *(float4*)&Hs[rr][kv*4] =
                    *(const float4*)(hin + (size_t)rr*512 + k0 + kv*4);
            }
            __syncthreads();
#pragma unroll
            for (int kv = 0; kv < 16; kv++) {
                float4 h0 = *(const float4*)&Hs[rp][kv*4];
                float4 wrv = *(const float4*)&wsh[(size_t)j*516 + k0 + kv*4];
                float4 wzv = *(const float4*)&wsh[(size_t)(8+j)*516 + k0 + kv*4];
                float4 wnv = *(const float4*)&wsh[(size_t)(16+j)*516 + k0 + kv*4];
                ar = dot4(h0, wrv, ar);
                az = dot4(h0, wzv, az);
                an = dot4(h0, wnv, an);
            }
            __syncthreads();
        }
        size_t grow = (size_t)rp*64 + tt;
        float gxr = gx[grow*1536 + jg];
        float gxz = gx[grow*1536 + 512 + jg];
        float gxn = gx[grow*1536 + 1024 + jg];
        float rr = sigm(gxr + ar + br);
        float zz = sigm(gxz + az + bz);
        float nn = tanhf(gxn + rr * (an + bnn));
        float hold = hin[(size_t)rp*512 + jg];
        float hnew = (1.f - zz) * nn + zz * hold;
        bool m = tt < sl;
        hout[(size_t)rp*512 + jg] = m ? hnew : hold;
        srch[grow*1024 + (size_t)dir*512 + jg] = __float2bfloat16(m ? hnew : 0.f);
    }
}

// ---------------------------------------------------------------------------
// Persistent decoder: 128 blocks x 256 thr, 64 steps.
//   blocks   0-31 : A — Uh[b] smem-resident; scores/softmax; publish alpha
//   blocks  32-63 : Q — qs = A_W-slice @ h (A_W smem-resident)
//   blocks 64-127 : G — gh = h@Whh^T (Whh smem-resident); ctx from bf16 P^T;
//                       pointwise GRU
// barriers: idx1 = h ready (128), idx2 = qs ready (A+Q, 64), idx3 = alpha (128)
// dyn smem = 131072 B (A role: Uh 64x512 fp32)
// ---------------------------------------------------------------------------
__global__ __launch_bounds__(256) void k_dec_all(
    const float* __restrict__ A_W, const float* __restrict__ A_b,
    const float* __restrict__ A_v, const float* __restrict__ Whh,
    const float* __restrict__ bhh, const int* __restrict__ slen,
    const int* __restrict__ tlen)
{
    extern __shared__ float dsm[];
    __shared__ float Hs[32][68];
    __shared__ float es[64];

    int bid = blockIdx.x;
    int t = threadIdx.x;
    int lane = t & 31;
    bool isA = bid < 32;
    bool isQ = (bid >= 32 && bid < 64);
    bool isG = bid >= 64;
    int b   = bid;          // A batch
    int qid = bid - 32;     // Q col group (16 q-cols)
    int j0  = (bid - 64) * 8;  // G h-col group

    float avr[16], qb0 = 0.f, qb1 = 0.f;
    if (isA) {
        for (int i = t; i < 8192; i += 256)
            *(float4*)&dsm[(size_t)i*4] =
                *(const float4*)(g_buf + OF_UH + (size_t)b*32768 + (size_t)i*4);
#pragma unroll
        for (int k = 0; k < 16; k++) avr[k] = A_v[lane + 32*k];
    }
    if (isQ) {
        for (int i = t; i < 16 * 128; i += 256) {
            int r = i >> 7, c4 = (i & 127) * 4;
            *(float4*)&dsm[r * 516 + c4] =
                *(const float4*)(A_W + (size_t)(qid*16 + r) * 512 + c4);
        }
        qb0 = A_b[qid*16 + (t & 15)];
        qb1 = A_b[qid*16 + ((t + 256) & 15)];
    }
    if (isG) {
        for (int i = t; i < 24 * 128; i += 256) {
            int wr = i >> 7, c4 = (i & 127) * 4;
            int gw = (wr >> 3) * 512 + j0 + (wr & 7);
            *(float4*)&dsm[wr * 516 + c4] =
                *(const float4*)(Whh + (size_t)gw * 512 + c4);
        }
    }
    __syncthreads();

    int rp = t >> 3, j = t & 7, jg = j0 + j;
    float br = 0.f, bz = 0.f, bnn = 0.f;
    int tl = 64;
    if (isG) {
        br = bhh[jg]; bz = bhh[512 + jg]; bnn = bhh[1024 + jg];
        tl = tlen[rp];
    }
    int sl = isA ? slen[b] : 0;
    const __nv_bfloat16* Pt = ((const __nv_bfloat16*)g_buf) + 2*OF_PB;

    for (int step = 0; step < 64; step++) {
        if (step > 0) gridbar(1, (unsigned)(step - 1), 128);   // h published
        int pin = step & 1;
        const float* hin = g_buf + OF_HD + (size_t)pin * 16384;
        float* hout = g_buf + OF_HD + (size_t)(pin ^ 1) * 16384;

        // ---- Q: qs = A_W @ h ----
        if (isQ) {
#pragma unroll
            for (int p = 0; p < 2; p++) {
                int pr = t + p * 256;
                int bb = pr >> 4, jj = pr & 15;
                const float* hrow = hin + (size_t)bb * 512;
                float acc = p ? qb1 : qb0;
                for (int k = 0; k < 512; k += 4)
                    acc = dot4(*(const float4*)&dsm[(size_t)jj*516 + k],
                               *(const float4*)(hrow + k), acc);
                g_buf[OF_QS + (size_t)bb * 512 + qid*16 + jj] = acc;
            }
        }
        if (bid < 64) gridbar(2, (unsigned)step, 64);          // qs ready (A+Q)

        // ---- A: scores + softmax -> alpha ----
        if (isA) {
            float qr[16];
#pragma unroll
            for (int k = 0; k < 16; k++)
                qr[k] = g_buf[OF_QS + (size_t)b*512 + lane + 32*k];
            int w = t >> 5;
#pragma unroll
            for (int si = 0; si < 8; si++) {
                int s = w*8 + si;
                float acc = 0.f;
#pragma unroll
                for (int k = 0; k < 16; k++) {
                    float x = dsm[(size_t)s*512 + lane + 32*k] + qr[k];
                    float th;
                    asm("tanh.approx.f32 %0, %1;" : "=f"(th) : "f"(x));
                    acc = fmaf(avr[k], th, acc);
                }
#pragma unroll
                for (int o = 16; o > 0; o >>= 1)
                    acc += __shfl_xor_sync(0xffffffffu, acc, o);
                if (lane == 0) es[s] = (s < sl) ? acc : acc - 1e9f;
            }
            __syncthreads();
            if (t < 32) {
                float a0 = es[t], a1 = es[t + 32];
                float m = fmaxf(a0, a1);
#pragma unroll
                for (int o = 16; o > 0; o >>= 1)
                    m = fmaxf(m, __shfl_xor_sync(0xffffffffu, m, o));
                float e0 = __expf(a0 - m), e1 = __expf(a1 - m);
                float sum = e0 + e1;
#pragma unroll
                for (int o = 16; o > 0; o >>= 1)
                    sum += __shfl_xor_sync(0xffffffffu, sum, o);
                es[t] = e0 / sum; es[t + 32] = e1 / sum;
            }
            __syncthreads();
            if (t < 64) g_buf[OF_AL + (size_t)b*64 + t] = es[t];
        }

        // ---- G: gate GEMM (overlaps Q/A since it skips bar idx2) ----
        float ar = 0.f, az = 0.f, an = 0.f;
        if (isG) {
            for (int k0 = 0; k0 < 512; k0 += 64) {
#pragma unroll
                for (int i = 0; i < 2; i++) {
                    int vec = t * 2 + i;           // 0..511
                    int rr = vec >> 4, kv = vec & 15;
                    *(float4*)&Hs[rr][kv*4] =
                        *(const float4*)(hin + (size_t)rr*512 + k0 + kv*4);
                }
                __syncthreads();
#pragma unroll
                for (int kv = 0; kv < 16; kv++) {
                    float4 h0 = *(const float4*)&Hs[rp][kv*4];
                    float4 wrv = *(const float4*)&dsm[(size_t)j*516 + k0 + kv*4];
                    float4 wzv = *(const float4*)&dsm[(size_t)(8+j)*516 + k0 + kv*4];
                    float4 wnv = *(const float4*)&dsm[(size_t)(16+j)*516 + k0 + kv*4];
                    ar = dot4(h0, wrv, ar);
                    az = dot4(h0, wzv, az);
                    an = dot4(h0, wnv, an);
                }
                __syncthreads();
            }
        }
        gridbar(3, (unsigned)step, 128);                       // alpha ready

        // ---- G: ctx from bf16 P^T + pointwise GRU ----
        if (isG) {
            for (int i = t; i < 2048; i += 256)
                Hs[i >> 6][i & 63] = g_buf[OF_AL + i];
            __syncthreads();
            float cr = 0.f, cz = 0.f, cn = 0.f;
            const uint4* p0 = (const uint4*)(Pt + (size_t)rp*98304 + (size_t)jg*64);
            const uint4* p1 = (const uint4*)(Pt + (size_t)rp*98304 + (size_t)(512 + jg)*64);
            const uint4* p2 = (const uint4*)(Pt + (size_t)rp*98304 + (size_t)(1024 + jg)*64);
#pragma unroll
            for (int q = 0; q < 8; q++) {
                uint4 v0 = p0[q], v1 = p1[q], v2 = p2[q];
                const __nv_bfloat16* h0 = (const __nv_bfloat16*)&v0;
                const __nv_bfloat16* h1 = (const __nv_bfloat16*)&v1;
                const __nv_bfloat16* h2 = (const __nv_bfloat16*)&v2;
#pragma unroll
                for (int u = 0; u < 8; u++) {
                    float al = Hs[rp][q*8 + u];
                    cr = fmaf(al, __bfloat162float(h0[u]), cr);
                    cz = fmaf(al, __bfloat162float(h1[u]), cz);
                    cn = fmaf(al, __bfloat162float(h2[u]), cn);
                }
            }
            size_t grow = (size_t)rp*64 + step;
            const float* gx = g_buf + OF_DGX + grow*1536;
            float rr = sigm(gx[jg]        + cr + ar + br);
            float zz = sigm(gx[512 + jg]  + cz + az + bz);
            float nn = tanhf(gx[1024 + jg] + cn + rr * (an + bnn));
            float hold = hin[(size_t)rp*512 + jg];
            float hnew = (1.f - zz) * nn + zz * hold;
            bool m = step < tl;
            hout[(size_t)rp*512 + jg] = m ? hnew : hold;
            g_buf[OF_DOUT + grow*512 + jg] = m ? hnew : 0.f;
        }
    }
}

// ---------------------------------------------------------------------------
// Per-row: combine partials (live rows) or shared logZ0 (zero rows)
// ---------------------------------------------------------------------------
__global__ __launch_bounds__(256) void k_combine(
    const int* __restrict__ tgt, const float* __restrict__ out_w,
    const float* __restrict__ out_b, const int* __restrict__ tlen)
{
    int row = blockIdx.x * 8 + (threadIdx.x >> 5);
    int lane = threadIdx.x & 31;
    int b = row >> 6, tc = row & 63;
    int goal = (tc < 63) ? tgt[b*64 + tc + 1] : 0;
    float contrib = 0.f, cnt = 0.f;
    if (goal != 0) {
        bool live = tc < tlen[b];
        float M, L, d = 0.f;
        if (live) {
            const float* p = g_buf + OF_LP + (size_t)row * 500;
            M = -1e30f;
            for (int c = lane; c < 250; c += 32) M = fmaxf(M, p[c*2]);
#pragma unroll
            for (int o = 16; o > 0; o >>= 1)
                M = fmaxf(M, __shfl_xor_sync(0xffffffffu, M, o));
            L = 0.f;
            for (int c = lane; c < 250; c += 32) L += p[c*2+1] * __expf(p[c*2] - M);
#pragma unroll
            for (int o = 16; o > 0; o >>= 1)
                L += __shfl_xor_sync(0xffffffffu, L, o);
            const float* x = g_buf + OF_DOUT + (size_t)row * 512;
            const float* wrow = out_w + (size_t)goal * 512;
            for (int k = lane; k < 512; k += 32) d = fmaf(x[k], wrow[k], d);
#pragma unroll
            for (int o = 16; o > 0; o >>= 1)
                d += __shfl_xor_sync(0xffffffffu, d, o);
        } else {
            M = g_M0; L = g_L0;
        }
        contrib = (d + out_b[goal]) - (M + logf(L));
        cnt = 1.f;
    }
    if (lane == 0) {
        g_buf[OF_CON + row] = contrib;
        g_buf[OF_CNT + row] = cnt;
    }
}

// ---------------------------------------------------------------------------
// Final deterministic reduce -> loss
// ---------------------------------------------------------------------------
__global__ void k_final(float* out) {
    __shared__ float sc[1024], sn[1024];
    int t = threadIdx.x;
    sc[t] = g_buf[OF_CON + t] + g_buf[OF_CON + 1024 + t];
    sn[t] = g_buf[OF_CNT + t] + g_buf[OF_CNT + 1024 + t];
    __syncthreads();
    for (int o = 512; o > 0; o >>= 1) {
        if (t < o) { sc[t] += sc[t+o]; sn[t] += sn[t+o]; }
        __syncthreads();
    }
    if (t == 0) out[0] = -sc[0] / sn[0];
}

// ---------------------------------------------------------------------------
// Host orchestration (graph-capturable: kernel launches only, default stream)
// ---------------------------------------------------------------------------
extern "C" void kernel_launch(void* const* d_in, const int* in_sizes, int n_in,
                              void* d_out, int out_size)
{
    const int*   src_seqs = (const int*)  d_in[0];
    const int*   src_len  = (const int*)  d_in[1];
    const int*   tgt_seqs = (const int*)  d_in[2];
    const int*   tgt_len  = (const int*)  d_in[3];
    const float* src_emb  = (const float*)d_in[4];
    const float* eWih_f   = (const float*)d_in[5];
    const float* eWhh_f   = (const float*)d_in[6];
    const float* ebih_f   = (const float*)d_in[7];
    const float* ebhh_f   = (const float*)d_in[8];
    const float* eWih_b   = (const float*)d_in[9];
    const float* eWhh_b   = (const float*)d_in[10];
    const float* ebih_b   = (const float*)d_in[11];
    const float* ebhh_b   = (const float*)d_in[12];
    const float* tgt_emb  = (const float*)d_in[13];
    const float* dWih     = (const float*)d_in[14];
    const float* dWhh     = (const float*)d_in[15];
    const float* dbih     = (const float*)d_in[16];
    const float* dbhh     = (const float*)d_in[17];
    const float* U_w      = (const float*)d_in[18];
    const float* U_b      = (const float*)d_in[19];
    const float* A_W      = (const float*)d_in[20];
    const float* A_b      = (const float*)d_in[21];
    const float* A_v      = (const float*)d_in[22];
    const float* out_w    = (const float*)d_in[23];
    const float* out_b    = (const float*)d_in[24];

    cudaFuncSetAttribute(k_enc_all, cudaFuncAttributeMaxDynamicSharedMemorySize, 49536);
    cudaFuncSetAttribute(k_dec_all, cudaFuncAttributeMaxDynamicSharedMemorySize, 131072);

    k_zero<<<64, 256>>>();
    k_compact<<<1, 256>>>(tgt_len);
    k_logz0<<<1, 1024>>>(out_b);

    // one-time bf16 weight conversions
    k_cvt_ext<<<384, 256>>>(eWih_f, OF_WF16, 98304);
    k_cvt_ext<<<384, 256>>>(eWih_b, OF_WB16, 98304);
    k_cvt_ext<<<1152, 256>>>(dWih, OF_WD16, 294912);
    k_cvt_ext<<<256, 256>>>(U_w, OF_UW16, 65536);
    k_cvt_ext<<<8000, 256>>>(out_w, OF_OW16, 2048000);

    k_embed16<<<2048, 128>>>(src_seqs, src_emb, OF_ESRCB);
    k_embed16<<<2048, 128>>>(tgt_seqs, tgt_emb, OF_ETGTB);

    // fused gate pre-GEMMs (GXF, GXB, DGX) in one launch
    k_gates16<<<dim3(36, 16), 256, 40960>>>(ebih_f, ebih_b, dbih);

    // persistent bidirectional encoder (single launch, 64 steps)
    k_enc_all<<<128, 256, 49536>>>(eWhh_f, ebhh_f, eWhh_b, ebhh_b, src_len);

    // Uh = srch @ U_w^T + U_b (fp32 out); P = srch @ Wih_ctx^T (bf16 transposed)
    k_gemm16<<<dim3(4, 16), 256, 40960>>>(2*OF_SRCHB, 1024, 2*OF_UW16, 1024,
                                          U_b, OF_UH, 512, 1024, 0);
    k_gemm16<<<dim3(12, 16), 256, 40960>>>(2*OF_SRCHB, 1024, 2*OF_WD16 + 512, 1536,
                                           (const float*)0, OF_PB, 0, 1024, 1);

    // persistent decoder (single launch, 64 steps, role-scoped barriers)
    k_dec_all<<<128, 256, 131072>>>(A_W, A_b, A_v, dWhh, dbhh, src_len, tgt_len);

    // logits: bf16 convert + compacted-row GEMM with fused log-softmax partials
    k_cvt_int<<<512, 256>>>(OF_DOUT, OF_DOB, 131072);
    k_logits16<<<dim3(250, 16), 256, 40960>>>(out_b);
    k_combine<<<256, 256>>>(tgt_seqs, out_w, out_b, tgt_len);
    k_final<<<1, 1024>>>((float*)d_out);
}